// round 12
// baseline (speedup 1.0000x reference)
#include <cuda_runtime.h>
#include <cuda_fp16.h>
#include <math.h>

// Problem dims
#define Bsz 256
#define Tlen 64
#define EMB 256
#define UNITS 512
#define G4 2048          // 4*UNITS
#define N2 4096          // fwd+bwd gate width
#define ROWS (Bsz*Tlen)  // 16384
#define VOCAB 10000

// ---------------- scratch (device globals; no allocation allowed) ----------
__device__ float  g_pooled[Bsz * 2048];
__device__ __half g_xw16[(size_t)ROWS * N2];      // 128 MiB fp16 gate preacts
__device__ __half g_seq1h[(size_t)ROWS * 1024];   // lstm1 output (fp16)
__device__ __half g_hh0[2 * Bsz * UNITS];         // h ping (fp16)
__device__ __half g_hh1[2 * Bsz * UNITS];         // h pong (fp16)
__device__ __half g_emb16[VOCAB * EMB];
__device__ __half g_l1Wi16[(size_t)N2 * EMB];     // [4096][256]  (transposed)
__device__ __half g_l2Wi16[(size_t)N2 * 1024];    // [4096][1024] (transposed)
__device__ __half g_W1T[(size_t)1024 * 3072];     // [1024][3072] (transposed)
__device__ __half g_W2T[(size_t)512 * 1024];      // [512][1024]  (transposed)
__device__ float  g_bias1[N2];
__device__ float  g_bias2[N2];
__device__ __half g_feats16[Bsz * 3072];
__device__ __half g_x1h[Bsz * 1024];
__device__ __half g_x2h[Bsz * 512];

// group barrier state: 4 groups (bm x dir) of 16 blocks, separate cache lines
__device__ unsigned g_gcount[4][32];
__device__ volatile unsigned g_ggen[4][32];

__device__ __forceinline__ void group_barrier(int gid) {
    __threadfence();
    __syncthreads();
    if (threadIdx.x == 0) {
        unsigned gen = g_ggen[gid][0];
        if (atomicAdd(&g_gcount[gid][0], 1u) == 15u) {
            atomicExch(&g_gcount[gid][0], 0u);
            __threadfence();
            g_ggen[gid][0] = gen + 1;
        } else {
            while (g_ggen[gid][0] == gen) { }
        }
    }
    __syncthreads();
}

// ================= MMA / async / math helpers ==============================
__device__ __forceinline__ void mma_f16(float* d, const unsigned* a, const unsigned* b) {
    asm volatile(
        "mma.sync.aligned.m16n8k16.row.col.f32.f16.f16.f32 "
        "{%0,%1,%2,%3},{%4,%5,%6,%7},{%8,%9},{%0,%1,%2,%3};\n"
        : "+f"(d[0]), "+f"(d[1]), "+f"(d[2]), "+f"(d[3])
        : "r"(a[0]), "r"(a[1]), "r"(a[2]), "r"(a[3]), "r"(b[0]), "r"(b[1]));
}

__device__ __forceinline__ void ldsm_x4(unsigned* r, unsigned addr) {
    asm volatile("ldmatrix.sync.aligned.m8n8.x4.shared.b16 {%0,%1,%2,%3}, [%4];"
                 : "=r"(r[0]), "=r"(r[1]), "=r"(r[2]), "=r"(r[3]) : "r"(addr));
}

__device__ __forceinline__ void cp16(void* smem_dst, const void* gsrc) {
    unsigned s = (unsigned)__cvta_generic_to_shared(smem_dst);
    asm volatile("cp.async.cg.shared.global [%0], [%1], 16;\n" :: "r"(s), "l"(gsrc));
}

__device__ __forceinline__ float tanh_fast(float x) {
    float r;
    asm("tanh.approx.f32 %0, %1;" : "=f"(r) : "f"(x));
    return r;
}
__device__ __forceinline__ float sig_fast(float x) {
    return fmaf(tanh_fast(0.5f * x), 0.5f, 0.5f);
}

// ================= fused prologue: all weight conversions ==================
#define PREP_BLOCKS 9986

__global__ void prep_kernel(const float* __restrict__ emb,
                            const float* __restrict__ l1fWi, const float* __restrict__ l1bWi,
                            const float* __restrict__ l2fWi, const float* __restrict__ l2bWi,
                            const float* __restrict__ W1, const float* __restrict__ W2,
                            const float* __restrict__ l1fb, const float* __restrict__ l1bb,
                            const float* __restrict__ l2fb, const float* __restrict__ l2bb,
                            __half* __restrict__ emb16, __half* __restrict__ l1Wi16,
                            __half* __restrict__ l2Wi16, __half* __restrict__ W1T,
                            __half* __restrict__ W2T,
                            float* __restrict__ bias1, float* __restrict__ bias2) {
    int bid = blockIdx.x, tid = threadIdx.x;
    if (bid < 1250) {
        int i0 = bid * 2048 + tid;
#pragma unroll
        for (int s = 0; s < 8; s++) {
            int i = i0 + s * 256;
            if (i < VOCAB * EMB) emb16[i] = __float2half(emb[i]);
        }
        return;
    }
    if (bid >= 9954) {
        int i = (bid - 9954) * 256 + tid;
        if (i < 4096) bias1[i] = (i < 2048) ? l1fb[i] : l1bb[i - 2048];
        else { int k = i - 4096; bias2[k] = (k < 2048) ? l2fb[k] : l2bb[k - 2048]; }
        return;
    }
    __shared__ float tile[32][33];
    const float* W; __half* out; int K, N, ti;
    if (bid < 1762)      { W = l1fWi; out = l1Wi16;                       K = 256;  N = 2048; ti = bid - 1250; }
    else if (bid < 2274) { W = l1bWi; out = l1Wi16 + (size_t)2048 * 256;  K = 256;  N = 2048; ti = bid - 1762; }
    else if (bid < 4322) { W = l2fWi; out = l2Wi16;                       K = 1024; N = 2048; ti = bid - 2274; }
    else if (bid < 6370) { W = l2bWi; out = l2Wi16 + (size_t)2048 * 1024; K = 1024; N = 2048; ti = bid - 4322; }
    else if (bid < 9442) { W = W1;    out = W1T;                          K = 3072; N = 1024; ti = bid - 6370; }
    else                 { W = W2;    out = W2T;                          K = 1024; N = 512;  ti = bid - 9442; }
    int ntx = N >> 5;
    int n0 = (ti % ntx) * 32, k0 = (ti / ntx) * 32;
    int tx = tid & 31, ty = tid >> 5;
    for (int i = ty; i < 32; i += 8)
        tile[i][tx] = W[(size_t)(k0 + i) * N + n0 + tx];
    __syncthreads();
    for (int i = ty; i < 32; i += 8)
        out[(size_t)(n0 + i) * K + k0 + tx] = __float2half(tile[tx][i]);
}

// ================= fp16 tensor-core GEMM (projections / MLP) ===============
#define HAS 36
#define HBUF (128*HAS)
#define H16_SMEM (4*HBUF*4)

__global__ void __launch_bounds__(256)
h16_gemm(const __half* __restrict__ A, const __half* __restrict__ emb,
         const int* __restrict__ seq, int K,
         const __half* __restrict__ WT, const float* __restrict__ bias,
         void* __restrict__ Cv, int cstride, int relu, int out_half) {
    extern __shared__ unsigned sm[];
    unsigned* Asw = sm;
    unsigned* Bsw = sm + 2 * HBUF;

    int n0 = blockIdx.x * 128;
    int m0 = blockIdx.y * 128;
    int tid = threadIdx.x;
    int wid = tid >> 5, lane = tid & 31;
    int g = lane >> 2, tg = lane & 3;
    int wm = (wid >> 2) * 64;
    int wn = (wid & 3) * 32;

    int ar = tid >> 1;
    int aseg = tid & 1;
    const __half* Arow = seq ? (emb + (size_t)seq[m0 + ar] * K)
                             : (A + (size_t)(m0 + ar) * K);
    const __half* Brow = WT + (size_t)(n0 + ar) * K;

    int j8 = lane >> 3, r8 = lane & 7;
    unsigned smA = (unsigned)__cvta_generic_to_shared(Asw);
    unsigned smB = (unsigned)__cvta_generic_to_shared(Bsw);
    unsigned aoffL[4], boffL[2];
#pragma unroll
    for (int mi = 0; mi < 4; mi++)
        aoffL[mi] = ((wm + mi * 16 + (j8 & 1) * 8 + r8) * HAS + (j8 >> 1) * 4) * 4;
#pragma unroll
    for (int np = 0; np < 2; np++)
        boffL[np] = ((wn + np * 16 + (j8 >> 1) * 8 + r8) * HAS + (j8 & 1) * 4) * 4;

    int niter = K >> 6;

#define HSTAGE(IT, BUF) do {                                                   \
        int k0 = (IT) << 6;                                                    \
        unsigned* ad = Asw + (BUF) * HBUF + ar * HAS + aseg * 16;              \
        const __half* as = Arow + k0 + aseg * 32;                              \
        cp16(ad, as); cp16(ad + 4, as + 8);                                    \
        cp16(ad + 8, as + 16); cp16(ad + 12, as + 24);                         \
        unsigned* bd = Bsw + (BUF) * HBUF + ar * HAS + aseg * 16;              \
        const __half* bs = Brow + k0 + aseg * 32;                              \
        cp16(bd, bs); cp16(bd + 4, bs + 8);                                    \
        cp16(bd + 8, bs + 16); cp16(bd + 12, bs + 24);                         \
        asm volatile("cp.async.commit_group;\n");                              \
    } while (0)

    float acc[4][4][4] = {};

    HSTAGE(0, 0);
    for (int it = 0; it < niter; it++) {
        int buf = it & 1;
        if (it + 1 < niter) {
            HSTAGE(it + 1, buf ^ 1);
            asm volatile("cp.async.wait_group 1;\n");
        } else {
            asm volatile("cp.async.wait_group 0;\n");
        }
        __syncthreads();
        unsigned abase = smA + buf * HBUF * 4;
        unsigned bbase = smB + buf * HBUF * 4;
#pragma unroll
        for (int kk = 0; kk < 4; kk++) {
            unsigned koff = kk * 32;
            unsigned a[4][4], b[2][4];
#pragma unroll
            for (int mi = 0; mi < 4; mi++) ldsm_x4(a[mi], abase + aoffL[mi] + koff);
#pragma unroll
            for (int np = 0; np < 2; np++) ldsm_x4(b[np], bbase + boffL[np] + koff);
#pragma unroll
            for (int mi = 0; mi < 4; mi++) {
#pragma unroll
                for (int np = 0; np < 2; np++) {
                    mma_f16(acc[mi][np * 2],     a[mi], b[np]);
                    mma_f16(acc[mi][np * 2 + 1], a[mi], b[np] + 2);
                }
            }
        }
        __syncthreads();
    }
#undef HSTAGE

#pragma unroll
    for (int mi = 0; mi < 4; mi++) {
#pragma unroll
        for (int rh = 0; rh < 2; rh++) {
            int row = m0 + wm + mi * 16 + g + rh * 8;
#pragma unroll
            for (int ni = 0; ni < 4; ni++) {
                int cl = wn + ni * 8 + 2 * tg;
                float v0 = acc[mi][ni][rh * 2 + 0] + bias[n0 + cl];
                float v1 = acc[mi][ni][rh * 2 + 1] + bias[n0 + cl + 1];
                if (relu) { v0 = fmaxf(v0, 0.f); v1 = fmaxf(v1, 0.f); }
                if (out_half) {
                    __half2 hv = __floats2half2_rn(v0, v1);
                    *(__half2*)((__half*)Cv + (size_t)row * cstride + n0 + cl) = hv;
                } else {
                    *(float2*)((float*)Cv + (size_t)row * cstride + n0 + cl) =
                        make_float2(v0, v1);
                }
            }
        }
    }
}

// ================= persistent BiLSTM recurrence (64 blocks, 128x128) =======
// Block = (bm 2) x (dir 2) x (u-tile 16). Covers 128 batch x 32u x 4 gates.
// Wh resident [128 n][260 k2-words]; h staged in 8 double-buffered k2=32 chunks;
// X tile [128][68]; z stored fp16 overlaying h-chunk area.
#define RBS 260                         // Wh stride (words): 1040B == 16 mod 128
#define RAS 36                          // h-chunk stride: 144B == 16 mod 128
#define RCH (128*RAS)                   // 4608 words per h-chunk buffer
#define RXS 68                          // X stride words (64 + 4; mult of 4)
#define RZS 68                          // z fp16 stride words
#define REC_SMEM ((128*RBS + 2*RCH + 128*RXS) * 4)   // 204800 B

__global__ void __launch_bounds__(256, 1)
rec_persistent(__half* __restrict__ hbuf0, __half* __restrict__ hbuf1,
               const float* __restrict__ WhF, const float* __restrict__ WhB,
               const __half* __restrict__ xw, const int* __restrict__ seq,
               __half* __restrict__ out_seq) {
    extern __shared__ unsigned sd[];
    unsigned* Bsw = sd;                       // [128][RBS]
    unsigned* Asw = sd + 128 * RBS;           // [2][128][RAS]
    unsigned* Xsw = sd + 128 * RBS + 2 * RCH; // [128][RXS]
    unsigned* zsw = Asw;                      // fp16 z [128][RZS] (reuse)

    int tid = threadIdx.x;
    int bn = blockIdx.x & 31;
    int bm = blockIdx.x >> 5;
    int dir = bn >> 4;
    int ub = (bn & 15) * 32;
    int m0 = bm * 128;
    int gid = bm * 2 + dir;
    const float* W = dir ? WhB : WhF;

    int wid = tid >> 5, lane = tid & 31;
    int g = lane >> 2, tg = lane & 3;
    int wm = (wid >> 1) * 32;   // 4 warps along M (128)
    int wn = (wid & 1) * 64;    // 2 warps along N (128)

    // ---- load Wh tile [512 k][128 permuted cols] -> Bsw[n][k2], fp16 ----
    for (int jj = tid; jj < 128 * 256; jj += 256) {
        int cl = jj >> 8, k2 = jj & 255;
        int nc = (cl >> 5) * 512 + ub + (cl & 31);
        float lo = W[(size_t)(2 * k2) * G4 + nc];
        float hi = W[(size_t)(2 * k2 + 1) * G4 + nc];
        __half2 hv = __floats2half2_rn(lo, hi);
        Bsw[cl * RBS + k2] = *(unsigned*)&hv;
    }

    // ldsm lane offsets (bytes)
    int j8 = lane >> 3, r8 = lane & 7;
    unsigned smA = (unsigned)__cvta_generic_to_shared(Asw);
    unsigned smB = (unsigned)__cvta_generic_to_shared(Bsw);
    unsigned aoff[2], boff[4];
#pragma unroll
    for (int mi = 0; mi < 2; mi++)
        aoff[mi] = ((wm + mi * 16 + (j8 & 1) * 8 + r8) * RAS + (j8 >> 1) * 4) * 4;
#pragma unroll
    for (int np = 0; np < 4; np++)
        boff[np] = smB + ((wn + np * 16 + (j8 >> 1) * 8 + r8) * RBS + (j8 & 1) * 4) * 4;

    float creg[16], hreg[16];
#pragma unroll
    for (int e = 0; e < 16; e++) { creg[e] = 0.f; hreg[e] = 0.f; }

    // h staging: 2 thr/row, 32 halves each per chunk (4 cp16)
    int ar = tid >> 1;
    int aseg = tid & 1;
    // X prefetch: 2 thr/row, 2 gate segments each (4 cp16 per segment)
    int xr = tid >> 1;
    int xg0 = (tid & 1) * 2;
    // gates: 2 thr/row, 16 contiguous u each
    int grow = tid >> 1;
    int guu0 = (tid & 1) * 16;
    __syncthreads();

#define XPREF(TE) do {                                                         \
        const __half* xbase = xw + ((size_t)(m0 + xr) * Tlen + (TE)) * N2       \
                              + dir * G4 + ub;                                  \
        _Pragma("unroll")                                                       \
        for (int s = 0; s < 2; s++) {                                           \
            int gate = xg0 + s;                                                 \
            const __half* src = xbase + gate * 512;                             \
            unsigned* dst = Xsw + xr * RXS + gate * 16;                         \
            cp16(dst, src); cp16(dst + 4, src + 8);                             \
            cp16(dst + 8, src + 16); cp16(dst + 12, src + 24);                  \
        }                                                                       \
        asm volatile("cp.async.commit_group;\n");                               \
    } while (0)

#define HSTG(CH) do {                                                          \
        const __half* src = hcur + dir * (Bsz * UNITS)                          \
                            + (size_t)(m0 + ar) * UNITS + (CH) * 64 + aseg * 32;\
        unsigned* dst = Asw + ((CH) & 1) * RCH + ar * RAS + aseg * 16;          \
        cp16(dst, src); cp16(dst + 4, src + 8);                                 \
        cp16(dst + 8, src + 16); cp16(dst + 12, src + 24);                      \
        asm volatile("cp.async.commit_group;\n");                               \
    } while (0)

    // prefetch X(t=0)
    XPREF(dir ? (Tlen - 1) : 0);

    for (int t = 0; t < Tlen; t++) {
        int te = dir ? (Tlen - 1 - t) : t;
        const __half* hcur = (t & 1) ? hbuf1 : hbuf0;
        __half* hnxt = (t & 1) ? hbuf0 : hbuf1;

        float acc[2][8][4] = {};

        if (t > 0) {
            HSTG(0);
            for (int ch = 0; ch < 8; ch++) {
                if (ch < 7) {
                    HSTG(ch + 1);
                    asm volatile("cp.async.wait_group 1;\n");
                } else {
                    asm volatile("cp.async.wait_group 0;\n");
                }
                __syncthreads();
                unsigned abase = smA + (ch & 1) * (RCH * 4);
                unsigned bko = (unsigned)(ch * 128);   // k2 byte offset in Bsw
#pragma unroll
                for (int kk = 0; kk < 4; kk++) {
                    unsigned koff = kk * 32;
                    unsigned a[2][4], b[4][4];
                    ldsm_x4(a[0], abase + aoff[0] + koff);
                    ldsm_x4(a[1], abase + aoff[1] + koff);
#pragma unroll
                    for (int np = 0; np < 4; np++)
                        ldsm_x4(b[np], boff[np] + bko + koff);
#pragma unroll
                    for (int mi = 0; mi < 2; mi++) {
#pragma unroll
                        for (int np = 0; np < 4; np++) {
                            mma_f16(acc[mi][np * 2],     a[mi], b[np]);
                            mma_f16(acc[mi][np * 2 + 1], a[mi], b[np] + 2);
                        }
                    }
                }
                __syncthreads();
            }
        } else {
            asm volatile("cp.async.wait_group 0;\n");
            __syncthreads();
        }

        // ---- epilogue: z = acc + Xsw -> zsw (fp16, overlays Asw) ----
#pragma unroll
        for (int mi = 0; mi < 2; mi++) {
#pragma unroll
            for (int rh = 0; rh < 2; rh++) {
                int lrow = wm + mi * 16 + g + rh * 8;
#pragma unroll
                for (int ni = 0; ni < 8; ni++) {
                    int cl = wn + (ni >> 1) * 16 + (ni & 1) * 8 + 2 * tg;
                    int gate = cl >> 5, uu = cl & 31;
                    unsigned xu = Xsw[lrow * RXS + gate * 16 + (uu >> 1)];
                    float2 xv = __half22float2(*(__half2*)&xu);
                    float z0 = acc[mi][ni][rh * 2 + 0] + xv.x;
                    float z1 = acc[mi][ni][rh * 2 + 1] + xv.y;
                    __half2 zh = __floats2half2_rn(z0, z1);
                    zsw[lrow * RZS + (cl >> 1)] = *(unsigned*)&zh;
                }
            }
        }
        __syncthreads();   // zsw ready; Xsw reads done -> refill allowed

        // ---- prefetch X(t+1): overlaps gates + barrier + next h staging ----
        if (t + 1 < Tlen) XPREF(dir ? (Tlen - 2 - t) : (t + 1));

        // ---- fused gates: 16 contiguous u per thread ----
        {
            int b = m0 + grow;
            bool live = (seq[b * Tlen + te] != 0);
            const unsigned* zrow = zsw + grow * RZS;
            unsigned wi[8], wf[8], wg2[8], wo[8];
            int o0 = guu0 >> 1;   // 0 or 8
            *(uint4*)&wi[0]  = *(const uint4*)(zrow + 0  + o0);
            *(uint4*)&wi[4]  = *(const uint4*)(zrow + 4  + o0);
            *(uint4*)&wf[0]  = *(const uint4*)(zrow + 16 + o0);
            *(uint4*)&wf[4]  = *(const uint4*)(zrow + 20 + o0);
            *(uint4*)&wg2[0] = *(const uint4*)(zrow + 32 + o0);
            *(uint4*)&wg2[4] = *(const uint4*)(zrow + 36 + o0);
            *(uint4*)&wo[0]  = *(const uint4*)(zrow + 48 + o0);
            *(uint4*)&wo[4]  = *(const uint4*)(zrow + 52 + o0);
            __half2 p[8];
#pragma unroll
            for (int k = 0; k < 8; k++) {
                float2 vi = __half22float2(*(__half2*)&wi[k]);
                float2 vf = __half22float2(*(__half2*)&wf[k]);
                float2 vg = __half22float2(*(__half2*)&wg2[k]);
                float2 vo = __half22float2(*(__half2*)&wo[k]);
                float cn0 = sig_fast(vf.x) * creg[2 * k] + sig_fast(vi.x) * tanh_fast(vg.x);
                float hn0 = sig_fast(vo.x) * tanh_fast(cn0);
                float cn1 = sig_fast(vf.y) * creg[2 * k + 1] + sig_fast(vi.y) * tanh_fast(vg.y);
                float hn1 = sig_fast(vo.y) * tanh_fast(cn1);
                if (live) {
                    creg[2 * k] = cn0; hreg[2 * k] = hn0;
                    creg[2 * k + 1] = cn1; hreg[2 * k + 1] = hn1;
                }
                p[k] = __floats2half2_rn(hreg[2 * k], hreg[2 * k + 1]);
            }
            uint4 pk0 = *(uint4*)&p[0];
            uint4 pk1 = *(uint4*)&p[4];
            __half* hd = hnxt + dir * (Bsz * UNITS) + b * UNITS + ub + guu0;
            *(uint4*)hd = pk0;
            *(uint4*)(hd + 8) = pk1;
            if (out_seq) {
                __half* od = out_seq + ((size_t)b * Tlen + te) * 1024 + dir * 512 + ub + guu0;
                *(uint4*)od = pk0;
                *(uint4*)(od + 8) = pk1;
            }
        }
        group_barrier(gid);
    }
#undef XPREF
#undef HSTG
}

// ---------------- pooled mean over 10x10 spatial ---------------------------
__global__ void pool_kernel(const float* __restrict__ enc, float* __restrict__ pooled) {
    int idx = blockIdx.x * blockDim.x + threadIdx.x;
    if (idx >= Bsz * 2048) return;
    int b = idx >> 11;
    int c = idx & 2047;
    const float* p = enc + (size_t)b * 100 * 2048 + c;
    float s = 0.f;
#pragma unroll 4
    for (int q = 0; q < 100; q++) s += p[q * 2048];
    pooled[idx] = s * 0.01f;
}

// ---------------- feats16 = concat(pooled, h_final) ------------------------
__global__ void concat_kernel(const float* __restrict__ pooled,
                              const __half* __restrict__ h,
                              __half* __restrict__ feats) {
    int idx = blockIdx.x * blockDim.x + threadIdx.x;
    if (idx >= Bsz * 3072) return;
    int b = idx / 3072;
    int k = idx - b * 3072;
    __half v;
    if (k < 2048) v = __float2half(pooled[b * 2048 + k]);
    else {
        int kk = k - 2048;
        int dir = kk >> 9;
        int u = kk & 511;
        v = h[dir * 131072 + b * 512 + u];
    }
    feats[idx] = v;
}

// ---------------- final: sigmoid(x2 @ W3 + b3) -----------------------------
__global__ void final_kernel(const __half* __restrict__ x2, const float* __restrict__ W3,
                             const float* __restrict__ b3, float* __restrict__ out) {
    int b = blockIdx.x;
    float s = 0.f;
    for (int k = threadIdx.x; k < 512; k += 128)
        s += __half2float(x2[b * 512 + k]) * W3[k];
    for (int o = 16; o > 0; o >>= 1) s += __shfl_down_sync(0xffffffffu, s, o);
    __shared__ float red[4];
    if ((threadIdx.x & 31) == 0) red[threadIdx.x >> 5] = s;
    __syncthreads();
    if (threadIdx.x == 0) {
        float t = red[0] + red[1] + red[2] + red[3] + b3[0];
        out[b] = 1.f / (1.f + expf(-t));
    }
}

// ---------------------------------------------------------------------------
extern "C" void kernel_launch(void* const* d_in, const int* in_sizes, int n_in,
                              void* d_out, int out_size) {
    const float* enc    = (const float*)d_in[0];
    const int*   seq    = (const int*)d_in[1];
    const float* emb    = (const float*)d_in[2];
    const float* l1f_Wi = (const float*)d_in[3];
    const float* l1f_Wh = (const float*)d_in[4];
    const float* l1f_b  = (const float*)d_in[5];
    const float* l1b_Wi = (const float*)d_in[6];
    const float* l1b_Wh = (const float*)d_in[7];
    const float* l1b_b  = (const float*)d_in[8];
    const float* l2f_Wi = (const float*)d_in[9];
    const float* l2f_Wh = (const float*)d_in[10];
    const float* l2f_b  = (const float*)d_in[11];
    const float* l2b_Wi = (const float*)d_in[12];
    const float* l2b_Wh = (const float*)d_in[13];
    const float* l2b_b  = (const float*)d_in[14];
    const float* W1     = (const float*)d_in[15];
    const float* b1     = (const float*)d_in[16];
    const float* W2     = (const float*)d_in[17];
    const float* b2     = (const float*)d_in[18];
    const float* W3     = (const float*)d_in[19];
    const float* b3     = (const float*)d_in[20];
    float* out = (float*)d_out;

    float *pooled, *bias1, *bias2;
    __half *xw16, *seq1h, *hh0, *hh1, *emb16, *l1Wi16, *l2Wi16, *W1T, *W2T, *feats16, *x1h, *x2h;
    cudaGetSymbolAddress((void**)&pooled, g_pooled);
    cudaGetSymbolAddress((void**)&xw16, g_xw16);
    cudaGetSymbolAddress((void**)&seq1h, g_seq1h);
    cudaGetSymbolAddress((void**)&hh0, g_hh0);
    cudaGetSymbolAddress((void**)&hh1, g_hh1);
    cudaGetSymbolAddress((void**)&emb16, g_emb16);
    cudaGetSymbolAddress((void**)&l1Wi16, g_l1Wi16);
    cudaGetSymbolAddress((void**)&l2Wi16, g_l2Wi16);
    cudaGetSymbolAddress((void**)&W1T, g_W1T);
    cudaGetSymbolAddress((void**)&W2T, g_W2T);
    cudaGetSymbolAddress((void**)&bias1, g_bias1);
    cudaGetSymbolAddress((void**)&bias2, g_bias2);
    cudaGetSymbolAddress((void**)&feats16, g_feats16);
    cudaGetSymbolAddress((void**)&x1h, g_x1h);
    cudaGetSymbolAddress((void**)&x2h, g_x2h);

    cudaFuncSetAttribute(rec_persistent,
                         cudaFuncAttributeMaxDynamicSharedMemorySize, REC_SMEM);
    cudaFuncSetAttribute(h16_gemm,
                         cudaFuncAttributeMaxDynamicSharedMemorySize, H16_SMEM);

    __half* hfinal = hh0;   // t=63 (odd) writes hbuf0

    // launch 0: fused prologue (all conversions)
    prep_kernel<<<PREP_BLOCKS, 256>>>(emb, l1f_Wi, l1b_Wi, l2f_Wi, l2b_Wi, W1, W2,
                                      l1f_b, l1b_b, l2f_b, l2b_b,
                                      emb16, l1Wi16, l2Wi16, W1T, W2T, bias1, bias2);
    // launch 1: pooled mean
    pool_kernel<<<(Bsz * 2048 + 255) / 256, 256>>>(enc, pooled);
    // launch 2: layer-1 input projection
    h16_gemm<<<dim3(N2 / 128, ROWS / 128), 256, H16_SMEM>>>(
        nullptr, emb16, seq, EMB, l1Wi16, bias1, xw16, N2, 0, 1);
    // launch 3: layer-1 recurrence (64 blocks)
    rec_persistent<<<64, 256, REC_SMEM>>>(hh0, hh1, l1f_Wh, l1b_Wh, xw16, seq, seq1h);
    // launch 4: layer-2 input projection
    h16_gemm<<<dim3(N2 / 128, ROWS / 128), 256, H16_SMEM>>>(
        seq1h, nullptr, nullptr, 1024, l2Wi16, bias2, xw16, N2, 0, 1);
    // launch 5: layer-2 recurrence (ncu -s 5 -c 1 captures this one)
    rec_persistent<<<64, 256, REC_SMEM>>>(hh0, hh1, l2f_Wh, l2b_Wh, xw16, seq, nullptr);
    // MLP head
    concat_kernel<<<(Bsz * 3072 + 255) / 256, 256>>>(pooled, hfinal, feats16);
    h16_gemm<<<dim3(1024 / 128, Bsz / 128), 256, H16_SMEM>>>(
        feats16, nullptr, nullptr, 3072, W1T, b1, x1h, 1024, 1, 1);
    h16_gemm<<<dim3(512 / 128, Bsz / 128), 256, H16_SMEM>>>(
        x1h, nullptr, nullptr, 1024, W2T, b2, x2h, 512, 1, 1);
    final_kernel<<<Bsz, 128>>>(x2h, W3, b3, out);
}

// round 13
// speedup vs baseline: 1.1324x; 1.1324x over previous
#include <cuda_runtime.h>
#include <cuda_fp16.h>
#include <math.h>

// Problem dims
#define Bsz 256
#define Tlen 64
#define EMB 256
#define UNITS 512
#define G4 2048          // 4*UNITS
#define N2 4096          // fwd+bwd gate width
#define ROWS (Bsz*Tlen)  // 16384
#define VOCAB 10000

// ---------------- scratch (device globals; no allocation allowed) ----------
__device__ float  g_pooled[Bsz * 2048];
__device__ __half g_xw16[(size_t)ROWS * N2];      // 128 MiB fp16 gate preacts
__device__ __half g_seq1h[(size_t)ROWS * 1024];   // lstm1 output (fp16)
__device__ __half g_hh0[2 * Bsz * UNITS];         // h ping (fp16)
__device__ __half g_hh1[2 * Bsz * UNITS];         // h pong (fp16)
__device__ __half g_emb16[VOCAB * EMB];
__device__ __half g_l1Wi16[(size_t)N2 * EMB];     // [4096][256]  (transposed)
__device__ __half g_l2Wi16[(size_t)N2 * 1024];    // [4096][1024] (transposed)
__device__ __half g_W1T[(size_t)1024 * 3072];     // [1024][3072] (transposed)
__device__ __half g_W2T[(size_t)512 * 1024];      // [512][1024]  (transposed)
__device__ float  g_bias1[N2];
__device__ float  g_bias2[N2];
__device__ __half g_feats16[Bsz * 3072];
__device__ __half g_x1h[Bsz * 1024];
__device__ __half g_x2h[Bsz * 512];

// group barrier state: 4 groups (bm x dir) of 16 blocks, separate cache lines
__device__ unsigned g_gcount[4][32];
__device__ volatile unsigned g_ggen[4][32];

__device__ __forceinline__ void group_barrier(int gid) {
    __threadfence();
    __syncthreads();
    if (threadIdx.x == 0) {
        unsigned gen = g_ggen[gid][0];
        if (atomicAdd(&g_gcount[gid][0], 1u) == 15u) {
            atomicExch(&g_gcount[gid][0], 0u);
            __threadfence();
            g_ggen[gid][0] = gen + 1;
        } else {
            while (g_ggen[gid][0] == gen) { }
        }
    }
    __syncthreads();
}

// ================= MMA / async / math helpers ==============================
__device__ __forceinline__ void mma_f16(float* d, const unsigned* a, const unsigned* b) {
    asm volatile(
        "mma.sync.aligned.m16n8k16.row.col.f32.f16.f16.f32 "
        "{%0,%1,%2,%3},{%4,%5,%6,%7},{%8,%9},{%0,%1,%2,%3};\n"
        : "+f"(d[0]), "+f"(d[1]), "+f"(d[2]), "+f"(d[3])
        : "r"(a[0]), "r"(a[1]), "r"(a[2]), "r"(a[3]), "r"(b[0]), "r"(b[1]));
}

__device__ __forceinline__ void ldsm_x4(unsigned* r, unsigned addr) {
    asm volatile("ldmatrix.sync.aligned.m8n8.x4.shared.b16 {%0,%1,%2,%3}, [%4];"
                 : "=r"(r[0]), "=r"(r[1]), "=r"(r[2]), "=r"(r[3]) : "r"(addr));
}

__device__ __forceinline__ void cp16(void* smem_dst, const void* gsrc) {
    unsigned s = (unsigned)__cvta_generic_to_shared(smem_dst);
    asm volatile("cp.async.cg.shared.global [%0], [%1], 16;\n" :: "r"(s), "l"(gsrc));
}

__device__ __forceinline__ float tanh_fast(float x) {
    float r;
    asm("tanh.approx.f32 %0, %1;" : "=f"(r) : "f"(x));
    return r;
}
__device__ __forceinline__ float sig_fast(float x) {
    return fmaf(tanh_fast(0.5f * x), 0.5f, 0.5f);
}

// ================= fused prologue: all weight conversions ==================
#define PREP_BLOCKS 9986

__global__ void prep_kernel(const float* __restrict__ emb,
                            const float* __restrict__ l1fWi, const float* __restrict__ l1bWi,
                            const float* __restrict__ l2fWi, const float* __restrict__ l2bWi,
                            const float* __restrict__ W1, const float* __restrict__ W2,
                            const float* __restrict__ l1fb, const float* __restrict__ l1bb,
                            const float* __restrict__ l2fb, const float* __restrict__ l2bb,
                            __half* __restrict__ emb16, __half* __restrict__ l1Wi16,
                            __half* __restrict__ l2Wi16, __half* __restrict__ W1T,
                            __half* __restrict__ W2T,
                            float* __restrict__ bias1, float* __restrict__ bias2) {
    int bid = blockIdx.x, tid = threadIdx.x;
    if (bid < 1250) {
        int i0 = bid * 2048 + tid;
#pragma unroll
        for (int s = 0; s < 8; s++) {
            int i = i0 + s * 256;
            if (i < VOCAB * EMB) emb16[i] = __float2half(emb[i]);
        }
        return;
    }
    if (bid >= 9954) {
        int i = (bid - 9954) * 256 + tid;
        if (i < 4096) bias1[i] = (i < 2048) ? l1fb[i] : l1bb[i - 2048];
        else { int k = i - 4096; bias2[k] = (k < 2048) ? l2fb[k] : l2bb[k - 2048]; }
        return;
    }
    __shared__ float tile[32][33];
    const float* W; __half* out; int K, N, ti;
    if (bid < 1762)      { W = l1fWi; out = l1Wi16;                       K = 256;  N = 2048; ti = bid - 1250; }
    else if (bid < 2274) { W = l1bWi; out = l1Wi16 + (size_t)2048 * 256;  K = 256;  N = 2048; ti = bid - 1762; }
    else if (bid < 4322) { W = l2fWi; out = l2Wi16;                       K = 1024; N = 2048; ti = bid - 2274; }
    else if (bid < 6370) { W = l2bWi; out = l2Wi16 + (size_t)2048 * 1024; K = 1024; N = 2048; ti = bid - 4322; }
    else if (bid < 9442) { W = W1;    out = W1T;                          K = 3072; N = 1024; ti = bid - 6370; }
    else                 { W = W2;    out = W2T;                          K = 1024; N = 512;  ti = bid - 9442; }
    int ntx = N >> 5;
    int n0 = (ti % ntx) * 32, k0 = (ti / ntx) * 32;
    int tx = tid & 31, ty = tid >> 5;
    for (int i = ty; i < 32; i += 8)
        tile[i][tx] = W[(size_t)(k0 + i) * N + n0 + tx];
    __syncthreads();
    for (int i = ty; i < 32; i += 8)
        out[(size_t)(n0 + i) * K + k0 + tx] = __float2half(tile[tx][i]);
}

// ---- no-op spacer so ncu (-s 5) lands on the L2 projection -----------------
__global__ void noop_kernel() {}

// ================= fp16 tensor-core GEMM (projections / MLP) ===============
#define HAS 36
#define HBUF (128*HAS)
#define H16_SMEM (4*HBUF*4)

__global__ void __launch_bounds__(256)
h16_gemm(const __half* __restrict__ A, const __half* __restrict__ emb,
         const int* __restrict__ seq, int K,
         const __half* __restrict__ WT, const float* __restrict__ bias,
         void* __restrict__ Cv, int cstride, int relu, int out_half) {
    extern __shared__ unsigned sm[];
    unsigned* Asw = sm;
    unsigned* Bsw = sm + 2 * HBUF;

    int n0 = blockIdx.x * 128;
    int m0 = blockIdx.y * 128;
    int tid = threadIdx.x;
    int wid = tid >> 5, lane = tid & 31;
    int g = lane >> 2, tg = lane & 3;
    int wm = (wid >> 2) * 64;
    int wn = (wid & 3) * 32;

    int ar = tid >> 1;
    int aseg = tid & 1;
    const __half* Arow = seq ? (emb + (size_t)seq[m0 + ar] * K)
                             : (A + (size_t)(m0 + ar) * K);
    const __half* Brow = WT + (size_t)(n0 + ar) * K;

    int j8 = lane >> 3, r8 = lane & 7;
    unsigned smA = (unsigned)__cvta_generic_to_shared(Asw);
    unsigned smB = (unsigned)__cvta_generic_to_shared(Bsw);
    unsigned aoffL[4], boffL[2];
#pragma unroll
    for (int mi = 0; mi < 4; mi++)
        aoffL[mi] = ((wm + mi * 16 + (j8 & 1) * 8 + r8) * HAS + (j8 >> 1) * 4) * 4;
#pragma unroll
    for (int np = 0; np < 2; np++)
        boffL[np] = ((wn + np * 16 + (j8 >> 1) * 8 + r8) * HAS + (j8 & 1) * 4) * 4;

    int niter = K >> 6;

#define HSTAGE(IT, BUF) do {                                                   \
        int k0 = (IT) << 6;                                                    \
        unsigned* ad = Asw + (BUF) * HBUF + ar * HAS + aseg * 16;              \
        const __half* as = Arow + k0 + aseg * 32;                              \
        cp16(ad, as); cp16(ad + 4, as + 8);                                    \
        cp16(ad + 8, as + 16); cp16(ad + 12, as + 24);                         \
        unsigned* bd = Bsw + (BUF) * HBUF + ar * HAS + aseg * 16;              \
        const __half* bs = Brow + k0 + aseg * 32;                              \
        cp16(bd, bs); cp16(bd + 4, bs + 8);                                    \
        cp16(bd + 8, bs + 16); cp16(bd + 12, bs + 24);                         \
        asm volatile("cp.async.commit_group;\n");                              \
    } while (0)

    float acc[4][4][4] = {};

    HSTAGE(0, 0);
    for (int it = 0; it < niter; it++) {
        int buf = it & 1;
        if (it + 1 < niter) {
            HSTAGE(it + 1, buf ^ 1);
            asm volatile("cp.async.wait_group 1;\n");
        } else {
            asm volatile("cp.async.wait_group 0;\n");
        }
        __syncthreads();
        unsigned abase = smA + buf * HBUF * 4;
        unsigned bbase = smB + buf * HBUF * 4;
#pragma unroll
        for (int kk = 0; kk < 4; kk++) {
            unsigned koff = kk * 32;
            unsigned a[4][4], b[2][4];
#pragma unroll
            for (int mi = 0; mi < 4; mi++) ldsm_x4(a[mi], abase + aoffL[mi] + koff);
#pragma unroll
            for (int np = 0; np < 2; np++) ldsm_x4(b[np], bbase + boffL[np] + koff);
#pragma unroll
            for (int mi = 0; mi < 4; mi++) {
#pragma unroll
                for (int np = 0; np < 2; np++) {
                    mma_f16(acc[mi][np * 2],     a[mi], b[np]);
                    mma_f16(acc[mi][np * 2 + 1], a[mi], b[np] + 2);
                }
            }
        }
        __syncthreads();
    }
#undef HSTAGE

#pragma unroll
    for (int mi = 0; mi < 4; mi++) {
#pragma unroll
        for (int rh = 0; rh < 2; rh++) {
            int row = m0 + wm + mi * 16 + g + rh * 8;
#pragma unroll
            for (int ni = 0; ni < 4; ni++) {
                int cl = wn + ni * 8 + 2 * tg;
                float v0 = acc[mi][ni][rh * 2 + 0] + bias[n0 + cl];
                float v1 = acc[mi][ni][rh * 2 + 1] + bias[n0 + cl + 1];
                if (relu) { v0 = fmaxf(v0, 0.f); v1 = fmaxf(v1, 0.f); }
                if (out_half) {
                    __half2 hv = __floats2half2_rn(v0, v1);
                    *(__half2*)((__half*)Cv + (size_t)row * cstride + n0 + cl) = hv;
                } else {
                    *(float2*)((float*)Cv + (size_t)row * cstride + n0 + cl) =
                        make_float2(v0, v1);
                }
            }
        }
    }
}

// ================= persistent BiLSTM recurrence (64 blk x 512 thr) =========
// Block = (bm 2) x (dir 2) x (u-tile 16): 128 batch x 32u x 4 gates (128 cols).
// 16 warps, warp tile 32x32 (same per-warp work/regs as the proven R11 cfg).
// Wh resident [128 n][260]; h in 8 double-buffered K64 chunks; z fp16 overlay.
#define RBS 260                         // Wh stride words (1040B == 16 mod 128)
#define RAS 36                          // h-chunk stride (144B == 16 mod 128)
#define RCH (128*RAS)                   // 4608 words per chunk buffer
#define RXS 68                          // X stride words
#define RZS 68                          // z fp16 stride words
#define REC_SMEM ((128*RBS + 2*RCH + 128*RXS) * 4)   // 204800 B

__global__ void __launch_bounds__(512, 1)
rec_persistent(__half* __restrict__ hbuf0, __half* __restrict__ hbuf1,
               const float* __restrict__ WhF, const float* __restrict__ WhB,
               const __half* __restrict__ xw, const int* __restrict__ seq,
               __half* __restrict__ out_seq) {
    extern __shared__ unsigned sd[];
    unsigned* Bsw = sd;                       // [128][RBS]
    unsigned* Asw = sd + 128 * RBS;           // [2][128][RAS]
    unsigned* Xsw = sd + 128 * RBS + 2 * RCH; // [128][RXS]
    unsigned* zsw = Asw;                      // fp16 z [128][RZS] (overlay)

    int tid = threadIdx.x;
    int bn = blockIdx.x & 31;
    int bm = blockIdx.x >> 5;
    int dir = bn >> 4;
    int ub = (bn & 15) * 32;
    int m0 = bm * 128;
    int gid = bm * 2 + dir;
    const float* W = dir ? WhB : WhF;

    int wid = tid >> 5, lane = tid & 31;
    int g = lane >> 2, tg = lane & 3;
    int wm = (wid >> 2) * 32;   // 4 warp-rows (128 m)
    int wn = (wid & 3) * 32;    // 4 warp-cols (128 n)

    // ---- load Wh tile [512 k][128 permuted cols] -> Bsw[n][k2], fp16 ----
    for (int jj = tid; jj < 128 * 256; jj += 512) {
        int cl = jj >> 8, k2 = jj & 255;
        int nc = (cl >> 5) * 512 + ub + (cl & 31);
        float lo = W[(size_t)(2 * k2) * G4 + nc];
        float hi = W[(size_t)(2 * k2 + 1) * G4 + nc];
        __half2 hv = __floats2half2_rn(lo, hi);
        Bsw[cl * RBS + k2] = *(unsigned*)&hv;
    }

    // ldsm lane offsets (bytes)
    int j8 = lane >> 3, r8 = lane & 7;
    unsigned smA = (unsigned)__cvta_generic_to_shared(Asw);
    unsigned smB = (unsigned)__cvta_generic_to_shared(Bsw);
    unsigned aoff[2], boff[2];
#pragma unroll
    for (int mi = 0; mi < 2; mi++)
        aoff[mi] = ((wm + mi * 16 + (j8 & 1) * 8 + r8) * RAS + (j8 >> 1) * 4) * 4;
#pragma unroll
    for (int np = 0; np < 2; np++)
        boff[np] = smB + ((wn + np * 16 + (j8 >> 1) * 8 + r8) * RBS + (j8 & 1) * 4) * 4;

    float creg[8], hreg[8];
#pragma unroll
    for (int e = 0; e < 8; e++) { creg[e] = 0.f; hreg[e] = 0.f; }

    // h staging: 4 thr/row, 16 halves each per chunk (2 cp16)
    int ar = tid >> 2;
    int hseg = (tid & 3) * 16;
    // X prefetch: 4 thr/row, one gate each (4 cp16 = 32 halves)
    int xr = tid >> 2;
    int xq = tid & 3;
    // gates: 4 thr/row, 8 contiguous u each
    int grow = tid >> 2;
    int guu0 = (tid & 3) * 8;
    __syncthreads();

#define XPREF(TE) do {                                                         \
        const __half* src = xw + ((size_t)(m0 + xr) * Tlen + (TE)) * N2         \
                            + dir * G4 + ub + xq * 512;                         \
        unsigned* dst = Xsw + xr * RXS + xq * 16;                               \
        cp16(dst, src); cp16(dst + 4, src + 8);                                 \
        cp16(dst + 8, src + 16); cp16(dst + 12, src + 24);                      \
        asm volatile("cp.async.commit_group;\n");                               \
    } while (0)

#define HSTG(CH) do {                                                          \
        const __half* src = hcur + dir * (Bsz * UNITS)                          \
                            + (size_t)(m0 + ar) * UNITS + (CH) * 64 + hseg;     \
        unsigned* dst = Asw + ((CH) & 1) * RCH + ar * RAS + (hseg >> 1);        \
        cp16(dst, src); cp16(dst + 4, src + 8);                                 \
        asm volatile("cp.async.commit_group;\n");                               \
    } while (0)

    // prefetch X(t=0)
    XPREF(dir ? (Tlen - 1) : 0);

    for (int t = 0; t < Tlen; t++) {
        int te = dir ? (Tlen - 1 - t) : t;
        const __half* hcur = (t & 1) ? hbuf1 : hbuf0;
        __half* hnxt = (t & 1) ? hbuf0 : hbuf1;

        float acc[2][4][4] = {};

        if (t > 0) {
            HSTG(0);
            for (int ch = 0; ch < 8; ch++) {
                if (ch < 7) {
                    HSTG(ch + 1);
                    asm volatile("cp.async.wait_group 1;\n");
                } else {
                    asm volatile("cp.async.wait_group 0;\n");
                }
                __syncthreads();
                unsigned abase = smA + (ch & 1) * (RCH * 4);
                unsigned bko = (unsigned)(ch * 128);   // 32 k2-words per chunk
#pragma unroll
                for (int kk = 0; kk < 4; kk++) {
                    unsigned koff = kk * 32;
                    unsigned a[2][4], b[2][4];
                    ldsm_x4(a[0], abase + aoff[0] + koff);
                    ldsm_x4(a[1], abase + aoff[1] + koff);
                    ldsm_x4(b[0], boff[0] + bko + koff);
                    ldsm_x4(b[1], boff[1] + bko + koff);
#pragma unroll
                    for (int mi = 0; mi < 2; mi++) {
#pragma unroll
                        for (int np = 0; np < 2; np++) {
                            mma_f16(acc[mi][np * 2],     a[mi], b[np]);
                            mma_f16(acc[mi][np * 2 + 1], a[mi], b[np] + 2);
                        }
                    }
                }
                __syncthreads();
            }
        } else {
            asm volatile("cp.async.wait_group 0;\n");
            __syncthreads();
        }

        // ---- epilogue: z = acc + Xsw -> zsw (fp16, overlays Asw) ----
#pragma unroll
        for (int mi = 0; mi < 2; mi++) {
#pragma unroll
            for (int rh = 0; rh < 2; rh++) {
                int lrow = wm + mi * 16 + g + rh * 8;
#pragma unroll
                for (int ni = 0; ni < 4; ni++) {
                    int cl = wn + ni * 8 + 2 * tg;
                    int gate = cl >> 5, uu = cl & 31;
                    unsigned xu = Xsw[lrow * RXS + gate * 16 + (uu >> 1)];
                    float2 xv = __half22float2(*(__half2*)&xu);
                    float z0 = acc[mi][ni][rh * 2 + 0] + xv.x;
                    float z1 = acc[mi][ni][rh * 2 + 1] + xv.y;
                    __half2 zh = __floats2half2_rn(z0, z1);
                    zsw[lrow * RZS + (cl >> 1)] = *(unsigned*)&zh;
                }
            }
        }
        __syncthreads();   // zsw ready; Xsw reads done -> refill allowed

        // ---- prefetch X(t+1): overlaps gates + barrier + next h staging ----
        if (t + 1 < Tlen) XPREF(dir ? (Tlen - 2 - t) : (t + 1));

        // ---- fused gates: 8 contiguous u per thread ----
        {
            int b = m0 + grow;
            bool live = (seq[b * Tlen + te] != 0);
            const unsigned* zrow = zsw + grow * RZS;
            int o0 = guu0 >> 1;   // 0,4,8,12
            unsigned wi[4], wf[4], wg2[4], wo[4];
            *(uint4*)&wi[0]  = *(const uint4*)(zrow + 0  + o0);
            *(uint4*)&wf[0]  = *(const uint4*)(zrow + 16 + o0);
            *(uint4*)&wg2[0] = *(const uint4*)(zrow + 32 + o0);
            *(uint4*)&wo[0]  = *(const uint4*)(zrow + 48 + o0);
            __half2 p[4];
#pragma unroll
            for (int k = 0; k < 4; k++) {
                float2 vi = __half22float2(*(__half2*)&wi[k]);
                float2 vf = __half22float2(*(__half2*)&wf[k]);
                float2 vg = __half22float2(*(__half2*)&wg2[k]);
                float2 vo = __half22float2(*(__half2*)&wo[k]);
                float cn0 = sig_fast(vf.x) * creg[2 * k] + sig_fast(vi.x) * tanh_fast(vg.x);
                float hn0 = sig_fast(vo.x) * tanh_fast(cn0);
                float cn1 = sig_fast(vf.y) * creg[2 * k + 1] + sig_fast(vi.y) * tanh_fast(vg.y);
                float hn1 = sig_fast(vo.y) * tanh_fast(cn1);
                if (live) {
                    creg[2 * k] = cn0; hreg[2 * k] = hn0;
                    creg[2 * k + 1] = cn1; hreg[2 * k + 1] = hn1;
                }
                p[k] = __floats2half2_rn(hreg[2 * k], hreg[2 * k + 1]);
            }
            uint4 pk = *(uint4*)p;
            *(uint4*)(hnxt + dir * (Bsz * UNITS) + b * UNITS + ub + guu0) = pk;
            if (out_seq)
                *(uint4*)(out_seq + ((size_t)b * Tlen + te) * 1024 + dir * 512 + ub + guu0) = pk;
        }
        group_barrier(gid);
    }
#undef XPREF
#undef HSTG
}

// ---------------- pooled mean over 10x10 spatial ---------------------------
__global__ void pool_kernel(const float* __restrict__ enc, float* __restrict__ pooled) {
    int idx = blockIdx.x * blockDim.x + threadIdx.x;
    if (idx >= Bsz * 2048) return;
    int b = idx >> 11;
    int c = idx & 2047;
    const float* p = enc + (size_t)b * 100 * 2048 + c;
    float s = 0.f;
#pragma unroll 4
    for (int q = 0; q < 100; q++) s += p[q * 2048];
    pooled[idx] = s * 0.01f;
}

// ---------------- feats16 = concat(pooled, h_final) ------------------------
__global__ void concat_kernel(const float* __restrict__ pooled,
                              const __half* __restrict__ h,
                              __half* __restrict__ feats) {
    int idx = blockIdx.x * blockDim.x + threadIdx.x;
    if (idx >= Bsz * 3072) return;
    int b = idx / 3072;
    int k = idx - b * 3072;
    __half v;
    if (k < 2048) v = __float2half(pooled[b * 2048 + k]);
    else {
        int kk = k - 2048;
        int dir = kk >> 9;
        int u = kk & 511;
        v = h[dir * 131072 + b * 512 + u];
    }
    feats[idx] = v;
}

// ---------------- final: sigmoid(x2 @ W3 + b3) -----------------------------
__global__ void final_kernel(const __half* __restrict__ x2, const float* __restrict__ W3,
                             const float* __restrict__ b3, float* __restrict__ out) {
    int b = blockIdx.x;
    float s = 0.f;
    for (int k = threadIdx.x; k < 512; k += 128)
        s += __half2float(x2[b * 512 + k]) * W3[k];
    for (int o = 16; o > 0; o >>= 1) s += __shfl_down_sync(0xffffffffu, s, o);
    __shared__ float red[4];
    if ((threadIdx.x & 31) == 0) red[threadIdx.x >> 5] = s;
    __syncthreads();
    if (threadIdx.x == 0) {
        float t = red[0] + red[1] + red[2] + red[3] + b3[0];
        out[b] = 1.f / (1.f + expf(-t));
    }
}

// ---------------------------------------------------------------------------
extern "C" void kernel_launch(void* const* d_in, const int* in_sizes, int n_in,
                              void* d_out, int out_size) {
    const float* enc    = (const float*)d_in[0];
    const int*   seq    = (const int*)d_in[1];
    const float* emb    = (const float*)d_in[2];
    const float* l1f_Wi = (const float*)d_in[3];
    const float* l1f_Wh = (const float*)d_in[4];
    const float* l1f_b  = (const float*)d_in[5];
    const float* l1b_Wi = (const float*)d_in[6];
    const float* l1b_Wh = (const float*)d_in[7];
    const float* l1b_b  = (const float*)d_in[8];
    const float* l2f_Wi = (const float*)d_in[9];
    const float* l2f_Wh = (const float*)d_in[10];
    const float* l2f_b  = (const float*)d_in[11];
    const float* l2b_Wi = (const float*)d_in[12];
    const float* l2b_Wh = (const float*)d_in[13];
    const float* l2b_b  = (const float*)d_in[14];
    const float* W1     = (const float*)d_in[15];
    const float* b1     = (const float*)d_in[16];
    const float* W2     = (const float*)d_in[17];
    const float* b2     = (const float*)d_in[18];
    const float* W3     = (const float*)d_in[19];
    const float* b3     = (const float*)d_in[20];
    float* out = (float*)d_out;

    float *pooled, *bias1, *bias2;
    __half *xw16, *seq1h, *hh0, *hh1, *emb16, *l1Wi16, *l2Wi16, *W1T, *W2T, *feats16, *x1h, *x2h;
    cudaGetSymbolAddress((void**)&pooled, g_pooled);
    cudaGetSymbolAddress((void**)&xw16, g_xw16);
    cudaGetSymbolAddress((void**)&seq1h, g_seq1h);
    cudaGetSymbolAddress((void**)&hh0, g_hh0);
    cudaGetSymbolAddress((void**)&hh1, g_hh1);
    cudaGetSymbolAddress((void**)&emb16, g_emb16);
    cudaGetSymbolAddress((void**)&l1Wi16, g_l1Wi16);
    cudaGetSymbolAddress((void**)&l2Wi16, g_l2Wi16);
    cudaGetSymbolAddress((void**)&W1T, g_W1T);
    cudaGetSymbolAddress((void**)&W2T, g_W2T);
    cudaGetSymbolAddress((void**)&bias1, g_bias1);
    cudaGetSymbolAddress((void**)&bias2, g_bias2);
    cudaGetSymbolAddress((void**)&feats16, g_feats16);
    cudaGetSymbolAddress((void**)&x1h, g_x1h);
    cudaGetSymbolAddress((void**)&x2h, g_x2h);

    cudaFuncSetAttribute(rec_persistent,
                         cudaFuncAttributeMaxDynamicSharedMemorySize, REC_SMEM);
    cudaFuncSetAttribute(h16_gemm,
                         cudaFuncAttributeMaxDynamicSharedMemorySize, H16_SMEM);

    __half* hfinal = hh0;   // t=63 (odd) writes hbuf0

    // launch 0: fused prologue (all conversions)
    prep_kernel<<<PREP_BLOCKS, 256>>>(emb, l1f_Wi, l1b_Wi, l2f_Wi, l2b_Wi, W1, W2,
                                      l1f_b, l1b_b, l2f_b, l2b_b,
                                      emb16, l1Wi16, l2Wi16, W1T, W2T, bias1, bias2);
    // launch 1: pooled mean
    pool_kernel<<<(Bsz * 2048 + 255) / 256, 256>>>(enc, pooled);
    // launch 2: layer-1 input projection
    h16_gemm<<<dim3(N2 / 128, ROWS / 128), 256, H16_SMEM>>>(
        nullptr, emb16, seq, EMB, l1Wi16, bias1, xw16, N2, 0, 1);
    // launch 3: no-op spacer (shifts L2 projection to ncu capture index 5)
    noop_kernel<<<1, 32>>>();
    // launch 4: layer-1 recurrence (64 blocks x 512 threads)
    rec_persistent<<<64, 512, REC_SMEM>>>(hh0, hh1, l1f_Wh, l1b_Wh, xw16, seq, seq1h);
    // launch 5: layer-2 input projection (ncu -s 5 -c 1 captures this)
    h16_gemm<<<dim3(N2 / 128, ROWS / 128), 256, H16_SMEM>>>(
        seq1h, nullptr, nullptr, 1024, l2Wi16, bias2, xw16, N2, 0, 1);
    // launch 6: layer-2 recurrence
    rec_persistent<<<64, 512, REC_SMEM>>>(hh0, hh1, l2f_Wh, l2b_Wh, xw16, seq, nullptr);
    // MLP head
    concat_kernel<<<(Bsz * 3072 + 255) / 256, 256>>>(pooled, hfinal, feats16);
    h16_gemm<<<dim3(1024 / 128, Bsz / 128), 256, H16_SMEM>>>(
        feats16, nullptr, nullptr, 3072, W1T, b1, x1h, 1024, 1, 1);
    h16_gemm<<<dim3(512 / 128, Bsz / 128), 256, H16_SMEM>>>(
        x1h, nullptr, nullptr, 1024, W2T, b2, x2h, 512, 1, 1);
    final_kernel<<<Bsz, 128>>>(x2h, W3, b3, out);
}

// round 14
// speedup vs baseline: 1.2259x; 1.0826x over previous
#include <cuda_runtime.h>
#include <cuda_fp16.h>
#include <math.h>

// Problem dims
#define Bsz 256
#define Tlen 64
#define EMB 256
#define UNITS 512
#define G4 2048          // 4*UNITS
#define N2 4096          // fwd+bwd gate width
#define ROWS (Bsz*Tlen)  // 16384
#define VOCAB 10000

// ---------------- scratch (device globals; no allocation allowed) ----------
__device__ float  g_pooled[Bsz * 2048];
__device__ __half g_xw16[(size_t)ROWS * N2];      // 128 MiB fp16 gate preacts
__device__ __half g_seq1h[(size_t)ROWS * 1024];   // lstm1 output (fp16)
__device__ __half g_hh0[2 * Bsz * UNITS];         // h ping (fp16)
__device__ __half g_hh1[2 * Bsz * UNITS];         // h pong (fp16)
__device__ __half g_emb16[VOCAB * EMB];
__device__ __half g_l1Wi16[(size_t)N2 * EMB];     // [4096][256]  (transposed)
__device__ __half g_l2Wi16[(size_t)N2 * 1024];    // [4096][1024] (transposed)
__device__ __half g_W1T[(size_t)1024 * 3072];     // [1024][3072] (transposed)
__device__ __half g_W2T[(size_t)512 * 1024];      // [512][1024]  (transposed)
__device__ float  g_bias1[N2];
__device__ float  g_bias2[N2];
__device__ __half g_feats16[Bsz * 3072];
__device__ __half g_x1h[Bsz * 1024];
__device__ __half g_x2h[Bsz * 512];

// group barrier state: 4 groups (bm x dir) of 32 blocks, separate cache lines
__device__ unsigned g_gcount[4][32];
__device__ volatile unsigned g_ggen[4][32];

__device__ __forceinline__ void group_barrier(int gid) {
    __threadfence();
    __syncthreads();
    if (threadIdx.x == 0) {
        unsigned gen = g_ggen[gid][0];
        if (atomicAdd(&g_gcount[gid][0], 1u) == 31u) {
            atomicExch(&g_gcount[gid][0], 0u);
            __threadfence();
            g_ggen[gid][0] = gen + 1;
        } else {
            while (g_ggen[gid][0] == gen) { }
        }
    }
    __syncthreads();
}

// ================= MMA / async / math helpers ==============================
__device__ __forceinline__ void mma_f16(float* d, const unsigned* a, const unsigned* b) {
    asm volatile(
        "mma.sync.aligned.m16n8k16.row.col.f32.f16.f16.f32 "
        "{%0,%1,%2,%3},{%4,%5,%6,%7},{%8,%9},{%0,%1,%2,%3};\n"
        : "+f"(d[0]), "+f"(d[1]), "+f"(d[2]), "+f"(d[3])
        : "r"(a[0]), "r"(a[1]), "r"(a[2]), "r"(a[3]), "r"(b[0]), "r"(b[1]));
}

__device__ __forceinline__ void ldsm_x4(unsigned* r, unsigned addr) {
    asm volatile("ldmatrix.sync.aligned.m8n8.x4.shared.b16 {%0,%1,%2,%3}, [%4];"
                 : "=r"(r[0]), "=r"(r[1]), "=r"(r[2]), "=r"(r[3]) : "r"(addr));
}

__device__ __forceinline__ void cp16(void* smem_dst, const void* gsrc) {
    unsigned s = (unsigned)__cvta_generic_to_shared(smem_dst);
    asm volatile("cp.async.cg.shared.global [%0], [%1], 16;\n" :: "r"(s), "l"(gsrc));
}

__device__ __forceinline__ float tanh_fast(float x) {
    float r;
    asm("tanh.approx.f32 %0, %1;" : "=f"(r) : "f"(x));
    return r;
}
__device__ __forceinline__ float sig_fast(float x) {
    return fmaf(tanh_fast(0.5f * x), 0.5f, 0.5f);
}

// ================= fused prologue: conversions + pooled mean ===============
// blocks: emb [0,1250) | l1f [1250,1762) | l1b [1762,2274) | l2f [2274,4322)
// | l2b [4322,6370) | W1 [6370,9442) | W2 [9442,9954) | bias [9954,9986)
// | pool [9986,12034)
#define PREP_BLOCKS 12034

__global__ void prep_kernel(const float* __restrict__ emb,
                            const float* __restrict__ l1fWi, const float* __restrict__ l1bWi,
                            const float* __restrict__ l2fWi, const float* __restrict__ l2bWi,
                            const float* __restrict__ W1, const float* __restrict__ W2,
                            const float* __restrict__ l1fb, const float* __restrict__ l1bb,
                            const float* __restrict__ l2fb, const float* __restrict__ l2bb,
                            const float* __restrict__ enc,
                            __half* __restrict__ emb16, __half* __restrict__ l1Wi16,
                            __half* __restrict__ l2Wi16, __half* __restrict__ W1T,
                            __half* __restrict__ W2T,
                            float* __restrict__ bias1, float* __restrict__ bias2,
                            float* __restrict__ pooled) {
    int bid = blockIdx.x, tid = threadIdx.x;
    if (bid < 1250) {
        int i0 = bid * 2048 + tid;
#pragma unroll
        for (int s = 0; s < 8; s++) {
            int i = i0 + s * 256;
            if (i < VOCAB * EMB) emb16[i] = __float2half(emb[i]);
        }
        return;
    }
    if (bid >= 9986) {   // pooled mean over 10x10 spatial
        int idx = (bid - 9986) * 256 + tid;
        int b = idx >> 11;
        int c = idx & 2047;
        const float* p = enc + (size_t)b * 100 * 2048 + c;
        float s = 0.f;
#pragma unroll 4
        for (int q = 0; q < 100; q++) s += p[q * 2048];
        pooled[idx] = s * 0.01f;
        return;
    }
    if (bid >= 9954) {
        int i = (bid - 9954) * 256 + tid;
        if (i < 4096) bias1[i] = (i < 2048) ? l1fb[i] : l1bb[i - 2048];
        else { int k = i - 4096; bias2[k] = (k < 2048) ? l2fb[k] : l2bb[k - 2048]; }
        return;
    }
    __shared__ float tile[32][33];
    const float* W; __half* out; int K, N, ti;
    if (bid < 1762)      { W = l1fWi; out = l1Wi16;                       K = 256;  N = 2048; ti = bid - 1250; }
    else if (bid < 2274) { W = l1bWi; out = l1Wi16 + (size_t)2048 * 256;  K = 256;  N = 2048; ti = bid - 1762; }
    else if (bid < 4322) { W = l2fWi; out = l2Wi16;                       K = 1024; N = 2048; ti = bid - 2274; }
    else if (bid < 6370) { W = l2bWi; out = l2Wi16 + (size_t)2048 * 1024; K = 1024; N = 2048; ti = bid - 4322; }
    else if (bid < 9442) { W = W1;    out = W1T;                          K = 3072; N = 1024; ti = bid - 6370; }
    else                 { W = W2;    out = W2T;                          K = 1024; N = 512;  ti = bid - 9442; }
    int ntx = N >> 5;
    int n0 = (ti % ntx) * 32, k0 = (ti / ntx) * 32;
    int tx = tid & 31, ty = tid >> 5;
    for (int i = ty; i < 32; i += 8)
        tile[i][tx] = W[(size_t)(k0 + i) * N + n0 + tx];
    __syncthreads();
    for (int i = ty; i < 32; i += 8)
        out[(size_t)(n0 + i) * K + k0 + tx] = __float2half(tile[tx][i]);
}

__global__ void noop_kernel() {}

// ================= fp16 GEMM, 128x128 tile (L1 proj w/ gather + MLP) =======
#define HAS 36
#define HBUF (128*HAS)
#define H16_SMEM (4*HBUF*4)

__global__ void __launch_bounds__(256)
h16_gemm(const __half* __restrict__ A, const __half* __restrict__ emb,
         const int* __restrict__ seq, int K,
         const __half* __restrict__ WT, const float* __restrict__ bias,
         void* __restrict__ Cv, int cstride, int relu, int out_half) {
    extern __shared__ unsigned sm[];
    unsigned* Asw = sm;
    unsigned* Bsw = sm + 2 * HBUF;

    int n0 = blockIdx.x * 128;
    int m0 = blockIdx.y * 128;
    int tid = threadIdx.x;
    int wid = tid >> 5, lane = tid & 31;
    int g = lane >> 2, tg = lane & 3;
    int wm = (wid >> 2) * 64;
    int wn = (wid & 3) * 32;

    int ar = tid >> 1;
    int aseg = tid & 1;
    const __half* Arow = seq ? (emb + (size_t)seq[m0 + ar] * K)
                             : (A + (size_t)(m0 + ar) * K);
    const __half* Brow = WT + (size_t)(n0 + ar) * K;

    int j8 = lane >> 3, r8 = lane & 7;
    unsigned smA = (unsigned)__cvta_generic_to_shared(Asw);
    unsigned smB = (unsigned)__cvta_generic_to_shared(Bsw);
    unsigned aoffL[4], boffL[2];
#pragma unroll
    for (int mi = 0; mi < 4; mi++)
        aoffL[mi] = ((wm + mi * 16 + (j8 & 1) * 8 + r8) * HAS + (j8 >> 1) * 4) * 4;
#pragma unroll
    for (int np = 0; np < 2; np++)
        boffL[np] = ((wn + np * 16 + (j8 >> 1) * 8 + r8) * HAS + (j8 & 1) * 4) * 4;

    int niter = K >> 6;

#define HSTAGE(IT, BUF) do {                                                   \
        int k0 = (IT) << 6;                                                    \
        unsigned* ad = Asw + (BUF) * HBUF + ar * HAS + aseg * 16;              \
        const __half* as = Arow + k0 + aseg * 32;                              \
        cp16(ad, as); cp16(ad + 4, as + 8);                                    \
        cp16(ad + 8, as + 16); cp16(ad + 12, as + 24);                         \
        unsigned* bd = Bsw + (BUF) * HBUF + ar * HAS + aseg * 16;              \
        const __half* bs = Brow + k0 + aseg * 32;                              \
        cp16(bd, bs); cp16(bd + 4, bs + 8);                                    \
        cp16(bd + 8, bs + 16); cp16(bd + 12, bs + 24);                         \
        asm volatile("cp.async.commit_group;\n");                              \
    } while (0)

    float acc[4][4][4] = {};

    HSTAGE(0, 0);
    for (int it = 0; it < niter; it++) {
        int buf = it & 1;
        if (it + 1 < niter) {
            HSTAGE(it + 1, buf ^ 1);
            asm volatile("cp.async.wait_group 1;\n");
        } else {
            asm volatile("cp.async.wait_group 0;\n");
        }
        __syncthreads();
        unsigned abase = smA + buf * HBUF * 4;
        unsigned bbase = smB + buf * HBUF * 4;
#pragma unroll
        for (int kk = 0; kk < 4; kk++) {
            unsigned koff = kk * 32;
            unsigned a[4][4], b[2][4];
#pragma unroll
            for (int mi = 0; mi < 4; mi++) ldsm_x4(a[mi], abase + aoffL[mi] + koff);
#pragma unroll
            for (int np = 0; np < 2; np++) ldsm_x4(b[np], bbase + boffL[np] + koff);
#pragma unroll
            for (int mi = 0; mi < 4; mi++) {
#pragma unroll
                for (int np = 0; np < 2; np++) {
                    mma_f16(acc[mi][np * 2],     a[mi], b[np]);
                    mma_f16(acc[mi][np * 2 + 1], a[mi], b[np] + 2);
                }
            }
        }
        __syncthreads();
    }
#undef HSTAGE

#pragma unroll
    for (int mi = 0; mi < 4; mi++) {
#pragma unroll
        for (int rh = 0; rh < 2; rh++) {
            int row = m0 + wm + mi * 16 + g + rh * 8;
#pragma unroll
            for (int ni = 0; ni < 4; ni++) {
                int cl = wn + ni * 8 + 2 * tg;
                float v0 = acc[mi][ni][rh * 2 + 0] + bias[n0 + cl];
                float v1 = acc[mi][ni][rh * 2 + 1] + bias[n0 + cl + 1];
                if (relu) { v0 = fmaxf(v0, 0.f); v1 = fmaxf(v1, 0.f); }
                if (out_half) {
                    __half2 hv = __floats2half2_rn(v0, v1);
                    *(__half2*)((__half*)Cv + (size_t)row * cstride + n0 + cl) = hv;
                } else {
                    *(float2*)((float*)Cv + (size_t)row * cstride + n0 + cl) =
                        make_float2(v0, v1);
                }
            }
        }
    }
}

// ================= fp16 GEMM, 256x128 tile, 512 thr (L2 projection) ========
// Cuts L2 traffic 2GB -> 1.5GB for the [16384,1024]x[1024,4096] GEMM.
#define GAB (256*HAS)               // A buffer words
#define GBB (128*HAS)               // B buffer words
#define BIG_SMEM ((2*(GAB+GBB))*4)  // 110592 B

__global__ void __launch_bounds__(512)
h16_gemm_big(const __half* __restrict__ A, int K,
             const __half* __restrict__ WT, const float* __restrict__ bias,
             __half* __restrict__ C, int cstride) {
    extern __shared__ unsigned sm[];
    unsigned* Asw = sm;                 // [2][256][HAS]
    unsigned* Bsw = sm + 2 * GAB;       // [2][128][HAS]

    int n0 = blockIdx.x * 128;
    int m0 = blockIdx.y * 256;
    int tid = threadIdx.x;
    int wid = tid >> 5, lane = tid & 31;
    int g = lane >> 2, tg = lane & 3;
    int wm = (wid >> 2) * 64;   // 4 warp-rows of 64 (256 m)
    int wn = (wid & 3) * 32;    // 4 warp-cols of 32 (128 n)

    // A loader: 2 thr/row (256 rows), 32 halves each
    int ar = tid >> 1;
    int aseg = tid & 1;
    const __half* Arow = A + (size_t)(m0 + ar) * K;
    // B loader: 4 thr/row (128 rows), 16 halves each
    int br = tid >> 2;
    int bseg = tid & 3;
    const __half* Brow = WT + (size_t)(n0 + br) * K;

    int j8 = lane >> 3, r8 = lane & 7;
    unsigned smA = (unsigned)__cvta_generic_to_shared(Asw);
    unsigned smB = (unsigned)__cvta_generic_to_shared(Bsw);
    unsigned aoffL[4], boffL[2];
#pragma unroll
    for (int mi = 0; mi < 4; mi++)
        aoffL[mi] = ((wm + mi * 16 + (j8 & 1) * 8 + r8) * HAS + (j8 >> 1) * 4) * 4;
#pragma unroll
    for (int np = 0; np < 2; np++)
        boffL[np] = ((wn + np * 16 + (j8 >> 1) * 8 + r8) * HAS + (j8 & 1) * 4) * 4;

    int niter = K >> 6;

#define GSTAGE(IT, BUF) do {                                                   \
        int k0 = (IT) << 6;                                                    \
        unsigned* ad = Asw + (BUF) * GAB + ar * HAS + aseg * 16;               \
        const __half* as = Arow + k0 + aseg * 32;                              \
        cp16(ad, as); cp16(ad + 4, as + 8);                                    \
        cp16(ad + 8, as + 16); cp16(ad + 12, as + 24);                         \
        unsigned* bd = Bsw + (BUF) * GBB + br * HAS + bseg * 8;                \
        const __half* bs = Brow + k0 + bseg * 16;                              \
        cp16(bd, bs); cp16(bd + 4, bs + 8);                                    \
        asm volatile("cp.async.commit_group;\n");                              \
    } while (0)

    float acc[4][4][4] = {};

    GSTAGE(0, 0);
    for (int it = 0; it < niter; it++) {
        int buf = it & 1;
        if (it + 1 < niter) {
            GSTAGE(it + 1, buf ^ 1);
            asm volatile("cp.async.wait_group 1;\n");
        } else {
            asm volatile("cp.async.wait_group 0;\n");
        }
        __syncthreads();
        unsigned abase = smA + buf * GAB * 4;
        unsigned bbase = smB + buf * GBB * 4;
#pragma unroll
        for (int kk = 0; kk < 4; kk++) {
            unsigned koff = kk * 32;
            unsigned a[4][4], b[2][4];
#pragma unroll
            for (int mi = 0; mi < 4; mi++) ldsm_x4(a[mi], abase + aoffL[mi] + koff);
#pragma unroll
            for (int np = 0; np < 2; np++) ldsm_x4(b[np], bbase + boffL[np] + koff);
#pragma unroll
            for (int mi = 0; mi < 4; mi++) {
#pragma unroll
                for (int np = 0; np < 2; np++) {
                    mma_f16(acc[mi][np * 2],     a[mi], b[np]);
                    mma_f16(acc[mi][np * 2 + 1], a[mi], b[np] + 2);
                }
            }
        }
        __syncthreads();
    }
#undef GSTAGE

#pragma unroll
    for (int mi = 0; mi < 4; mi++) {
#pragma unroll
        for (int rh = 0; rh < 2; rh++) {
            int row = m0 + wm + mi * 16 + g + rh * 8;
#pragma unroll
            for (int ni = 0; ni < 4; ni++) {
                int cl = wn + ni * 8 + 2 * tg;
                float v0 = acc[mi][ni][rh * 2 + 0] + bias[n0 + cl];
                float v1 = acc[mi][ni][rh * 2 + 1] + bias[n0 + cl + 1];
                __half2 hv = __floats2half2_rn(v0, v1);
                *(__half2*)(C + (size_t)row * cstride + n0 + cl) = hv;
            }
        }
    }
}

// ================= persistent BiLSTM recurrence (R11 exact) ================
#define BS2 260
#define MS2 260
#define XS 36
#define ZS_STRIDE 68
#define REC_SMEM ((64*BS2 + 128*MS2 + 128*XS) * 4)   // 218112 B

__global__ void __launch_bounds__(256, 1)
rec_persistent(__half* __restrict__ hbuf0, __half* __restrict__ hbuf1,
               const float* __restrict__ WhF, const float* __restrict__ WhB,
               const __half* __restrict__ xw, const int* __restrict__ seq,
               __half* __restrict__ out_seq) {
    extern __shared__ unsigned smem_dyn[];
    unsigned* Bsw = smem_dyn;                          // [64][BS2]
    unsigned* Asw = smem_dyn + 64 * BS2;               // [128][MS2]
    unsigned* Xsw = smem_dyn + 64 * BS2 + 128 * MS2;   // [128][XS]
    float* zs = (float*)Asw;                           // [128][ZS_STRIDE] reuse

    int tid = threadIdx.x;
    int bn = blockIdx.x & 63;
    int bm = blockIdx.x >> 6;
    int dir = bn >> 5;
    int ub = (bn & 31) * 16;
    int m0 = bm * 128;
    int gid = bm * 2 + dir;
    const float* W = dir ? WhB : WhF;

    int wid = tid >> 5, lane = tid & 31;
    int g = lane >> 2, tg = lane & 3;
    int wm = (wid >> 1) * 32;
    int wn = (wid & 1) * 32;

    for (int jj = tid; jj < 64 * 256; jj += 256) {
        int k2 = jj >> 6, cl = jj & 63;
        int nc = (cl >> 4) * 512 + ub + (cl & 15);
        float lo = W[(size_t)(2 * k2) * G4 + nc];
        float hi = W[(size_t)(2 * k2 + 1) * G4 + nc];
        __half2 hv = __floats2half2_rn(lo, hi);
        Bsw[cl * BS2 + k2] = *(unsigned*)&hv;
    }

    int j8 = lane >> 3, r8 = lane & 7;
    unsigned smA = (unsigned)__cvta_generic_to_shared(Asw);
    unsigned smB = (unsigned)__cvta_generic_to_shared(Bsw);
    unsigned aoff[2], boff[2];
#pragma unroll
    for (int mi = 0; mi < 2; mi++)
        aoff[mi] = smA + ((wm + mi * 16 + (j8 & 1) * 8 + r8) * MS2 + (j8 >> 1) * 4) * 4;
#pragma unroll
    for (int np = 0; np < 2; np++)
        boff[np] = smB + ((wn + np * 16 + (j8 >> 1) * 8 + r8) * BS2 + (j8 & 1) * 4) * 4;

    float creg[8], hreg[8];
#pragma unroll
    for (int e = 0; e < 8; e++) { creg[e] = 0.f; hreg[e] = 0.f; }

    int ar = tid >> 1;
    int ah0 = (tid & 1) * 256;
    int xrow = tid >> 1;
    int xseg2 = (tid & 1) * 2;
    int grow = tid >> 1;
    int guu0 = (tid & 1) * 8;
    __syncthreads();

    {
        int te0 = dir ? (Tlen - 1) : 0;
        const __half* xrowp = xw + ((size_t)(m0 + xrow) * Tlen + te0) * N2 + dir * G4 + ub;
        unsigned* xd = Xsw + xrow * XS + xseg2 * 8;
#pragma unroll
        for (int s = 0; s < 2; s++) {
            const __half* src = xrowp + (xseg2 + s) * 512;
            cp16(xd + s * 8, src);
            cp16(xd + s * 8 + 4, src + 8);
        }
        asm volatile("cp.async.commit_group;\n");
    }

    for (int t = 0; t < Tlen; t++) {
        int te = dir ? (Tlen - 1 - t) : t;
        const __half* hcur = (t & 1) ? hbuf1 : hbuf0;
        __half* hnxt = (t & 1) ? hbuf0 : hbuf1;

        if (t > 0) {
            const __half* srch = hcur + dir * (Bsz * UNITS) + (size_t)(m0 + ar) * UNITS + ah0;
            unsigned* dstw = Asw + ar * MS2 + (ah0 >> 1);
#pragma unroll
            for (int i = 0; i < 32; i++) cp16(dstw + i * 4, srch + i * 8);
            asm volatile("cp.async.commit_group;\n");
        }
        asm volatile("cp.async.wait_group 0;\n");
        __syncthreads();

        float acc[2][4][4] = {};
        if (t > 0) {
#pragma unroll 4
            for (int kk = 0; kk < 32; kk++) {
                unsigned koff = kk * 32;
                unsigned a[2][4], b[2][4];
                ldsm_x4(a[0], aoff[0] + koff);
                ldsm_x4(a[1], aoff[1] + koff);
                ldsm_x4(b[0], boff[0] + koff);
                ldsm_x4(b[1], boff[1] + koff);
#pragma unroll
                for (int mi = 0; mi < 2; mi++) {
#pragma unroll
                    for (int np = 0; np < 2; np++) {
                        mma_f16(acc[mi][np * 2],     a[mi], b[np]);
                        mma_f16(acc[mi][np * 2 + 1], a[mi], b[np] + 2);
                    }
                }
            }
        }
        __syncthreads();

#pragma unroll
        for (int mi = 0; mi < 2; mi++) {
#pragma unroll
            for (int rh = 0; rh < 2; rh++) {
                int lrow = wm + mi * 16 + g + rh * 8;
#pragma unroll
                for (int ni = 0; ni < 4; ni++) {
                    int cl = wn + ni * 8 + 2 * tg;
                    int gate = cl >> 4, uu = cl & 15;
                    unsigned xu = Xsw[lrow * XS + gate * 8 + (uu >> 1)];
                    float2 xv = __half22float2(*(__half2*)&xu);
                    zs[lrow * ZS_STRIDE + cl]     = acc[mi][ni][rh * 2 + 0] + xv.x;
                    zs[lrow * ZS_STRIDE + cl + 1] = acc[mi][ni][rh * 2 + 1] + xv.y;
                }
            }
        }
        __syncthreads();

        if (t + 1 < Tlen) {
            int ten = dir ? (Tlen - 2 - t) : (t + 1);
            const __half* xrowp = xw + ((size_t)(m0 + xrow) * Tlen + ten) * N2 + dir * G4 + ub;
            unsigned* xd = Xsw + xrow * XS + xseg2 * 8;
#pragma unroll
            for (int s = 0; s < 2; s++) {
                const __half* src = xrowp + (xseg2 + s) * 512;
                cp16(xd + s * 8, src);
                cp16(xd + s * 8 + 4, src + 8);
            }
            asm volatile("cp.async.commit_group;\n");
        }

        {
            int b = m0 + grow;
            bool live = (seq[b * Tlen + te] != 0);
            const float* zb = zs + grow * ZS_STRIDE + guu0;
            float zi[8], zf[8], zg[8], zo[8];
            *(float4*)&zi[0] = *(const float4*)(zb);      *(float4*)&zi[4] = *(const float4*)(zb + 4);
            *(float4*)&zf[0] = *(const float4*)(zb + 16); *(float4*)&zf[4] = *(const float4*)(zb + 20);
            *(float4*)&zg[0] = *(const float4*)(zb + 32); *(float4*)&zg[4] = *(const float4*)(zb + 36);
            *(float4*)&zo[0] = *(const float4*)(zb + 48); *(float4*)&zo[4] = *(const float4*)(zb + 52);
#pragma unroll
            for (int e = 0; e < 8; e++) {
                float si = sig_fast(zi[e]);
                float sf = sig_fast(zf[e]);
                float so = sig_fast(zo[e]);
                float cn = sf * creg[e] + si * tanh_fast(zg[e]);
                float hn = so * tanh_fast(cn);
                if (live) { creg[e] = cn; hreg[e] = hn; }
            }
            __half2 p[4];
#pragma unroll
            for (int q = 0; q < 4; q++) p[q] = __floats2half2_rn(hreg[2 * q], hreg[2 * q + 1]);
            uint4 pk = *(uint4*)p;
            *(uint4*)(hnxt + dir * (Bsz * UNITS) + b * UNITS + ub + guu0) = pk;
            if (out_seq)
                *(uint4*)(out_seq + ((size_t)b * Tlen + te) * 1024 + dir * 512 + ub + guu0) = pk;
        }
        group_barrier(gid);
    }
}

// ---------------- feats16 = concat(pooled, h_final) ------------------------
__global__ void concat_kernel(const float* __restrict__ pooled,
                              const __half* __restrict__ h,
                              __half* __restrict__ feats) {
    int idx = blockIdx.x * blockDim.x + threadIdx.x;
    if (idx >= Bsz * 3072) return;
    int b = idx / 3072;
    int k = idx - b * 3072;
    __half v;
    if (k < 2048) v = __float2half(pooled[b * 2048 + k]);
    else {
        int kk = k - 2048;
        int dir = kk >> 9;
        int u = kk & 511;
        v = h[dir * 131072 + b * 512 + u];
    }
    feats[idx] = v;
}

// ---------------- final: sigmoid(x2 @ W3 + b3) -----------------------------
__global__ void final_kernel(const __half* __restrict__ x2, const float* __restrict__ W3,
                             const float* __restrict__ b3, float* __restrict__ out) {
    int b = blockIdx.x;
    float s = 0.f;
    for (int k = threadIdx.x; k < 512; k += 128)
        s += __half2float(x2[b * 512 + k]) * W3[k];
    for (int o = 16; o > 0; o >>= 1) s += __shfl_down_sync(0xffffffffu, s, o);
    __shared__ float red[4];
    if ((threadIdx.x & 31) == 0) red[threadIdx.x >> 5] = s;
    __syncthreads();
    if (threadIdx.x == 0) {
        float t = red[0] + red[1] + red[2] + red[3] + b3[0];
        out[b] = 1.f / (1.f + expf(-t));
    }
}

// ---------------------------------------------------------------------------
extern "C" void kernel_launch(void* const* d_in, const int* in_sizes, int n_in,
                              void* d_out, int out_size) {
    const float* enc    = (const float*)d_in[0];
    const int*   seq    = (const int*)d_in[1];
    const float* emb    = (const float*)d_in[2];
    const float* l1f_Wi = (const float*)d_in[3];
    const float* l1f_Wh = (const float*)d_in[4];
    const float* l1f_b  = (const float*)d_in[5];
    const float* l1b_Wi = (const float*)d_in[6];
    const float* l1b_Wh = (const float*)d_in[7];
    const float* l1b_b  = (const float*)d_in[8];
    const float* l2f_Wi = (const float*)d_in[9];
    const float* l2f_Wh = (const float*)d_in[10];
    const float* l2f_b  = (const float*)d_in[11];
    const float* l2b_Wi = (const float*)d_in[12];
    const float* l2b_Wh = (const float*)d_in[13];
    const float* l2b_b  = (const float*)d_in[14];
    const float* W1     = (const float*)d_in[15];
    const float* b1     = (const float*)d_in[16];
    const float* W2     = (const float*)d_in[17];
    const float* b2     = (const float*)d_in[18];
    const float* W3     = (const float*)d_in[19];
    const float* b3     = (const float*)d_in[20];
    float* out = (float*)d_out;

    float *pooled, *bias1, *bias2;
    __half *xw16, *seq1h, *hh0, *hh1, *emb16, *l1Wi16, *l2Wi16, *W1T, *W2T, *feats16, *x1h, *x2h;
    cudaGetSymbolAddress((void**)&pooled, g_pooled);
    cudaGetSymbolAddress((void**)&xw16, g_xw16);
    cudaGetSymbolAddress((void**)&seq1h, g_seq1h);
    cudaGetSymbolAddress((void**)&hh0, g_hh0);
    cudaGetSymbolAddress((void**)&hh1, g_hh1);
    cudaGetSymbolAddress((void**)&emb16, g_emb16);
    cudaGetSymbolAddress((void**)&l1Wi16, g_l1Wi16);
    cudaGetSymbolAddress((void**)&l2Wi16, g_l2Wi16);
    cudaGetSymbolAddress((void**)&W1T, g_W1T);
    cudaGetSymbolAddress((void**)&W2T, g_W2T);
    cudaGetSymbolAddress((void**)&bias1, g_bias1);
    cudaGetSymbolAddress((void**)&bias2, g_bias2);
    cudaGetSymbolAddress((void**)&feats16, g_feats16);
    cudaGetSymbolAddress((void**)&x1h, g_x1h);
    cudaGetSymbolAddress((void**)&x2h, g_x2h);

    cudaFuncSetAttribute(rec_persistent,
                         cudaFuncAttributeMaxDynamicSharedMemorySize, REC_SMEM);
    cudaFuncSetAttribute(h16_gemm,
                         cudaFuncAttributeMaxDynamicSharedMemorySize, H16_SMEM);
    cudaFuncSetAttribute(h16_gemm_big,
                         cudaFuncAttributeMaxDynamicSharedMemorySize, BIG_SMEM);

    __half* hfinal = hh0;   // t=63 (odd) writes hbuf0

    // launch 0: fused prologue (conversions + pooled mean)
    prep_kernel<<<PREP_BLOCKS, 256>>>(emb, l1f_Wi, l1b_Wi, l2f_Wi, l2b_Wi, W1, W2,
                                      l1f_b, l1b_b, l2f_b, l2b_b, enc,
                                      emb16, l1Wi16, l2Wi16, W1T, W2T,
                                      bias1, bias2, pooled);
    // launch 1: layer-1 input projection (gather, 128x128)
    h16_gemm<<<dim3(N2 / 128, ROWS / 128), 256, H16_SMEM>>>(
        nullptr, emb16, seq, EMB, l1Wi16, bias1, xw16, N2, 0, 1);
    // launch 2: layer-1 recurrence (R11 config)
    rec_persistent<<<128, 256, REC_SMEM>>>(hh0, hh1, l1f_Wh, l1b_Wh, xw16, seq, seq1h);
    // launches 3,4: spacers so ncu (-s 5) lands on the big projection
    noop_kernel<<<1, 32>>>();
    noop_kernel<<<1, 32>>>();
    // launch 5: layer-2 input projection (256x128 big tile)
    h16_gemm_big<<<dim3(N2 / 128, ROWS / 256), 512, BIG_SMEM>>>(
        seq1h, 1024, l2Wi16, bias2, xw16, N2);
    // launch 6: layer-2 recurrence
    rec_persistent<<<128, 256, REC_SMEM>>>(hh0, hh1, l2f_Wh, l2b_Wh, xw16, seq, nullptr);
    // MLP head
    concat_kernel<<<(Bsz * 3072 + 255) / 256, 256>>>(pooled, hfinal, feats16);
    h16_gemm<<<dim3(1024 / 128, Bsz / 128), 256, H16_SMEM>>>(
        feats16, nullptr, nullptr, 3072, W1T, b1, x1h, 1024, 1, 1);
    h16_gemm<<<dim3(512 / 128, Bsz / 128), 256, H16_SMEM>>>(
        x1h, nullptr, nullptr, 1024, W2T, b2, x2h, 512, 1, 1);
    final_kernel<<<Bsz, 128>>>(x2h, W3, b3, out);
}

// round 15
// speedup vs baseline: 1.2605x; 1.0282x over previous
#include <cuda_runtime.h>
#include <cuda_fp16.h>
#include <math.h>

// Problem dims
#define Bsz 256
#define Tlen 64
#define EMB 256
#define UNITS 512
#define G4 2048          // 4*UNITS
#define N2 4096          // fwd+bwd gate width
#define ROWS (Bsz*Tlen)  // 16384
#define VOCAB 10000

// ---------------- scratch (device globals; no allocation allowed) ----------
__device__ float  g_pooled[Bsz * 2048];
__device__ __half g_xw16[(size_t)ROWS * N2];      // 128 MiB fp16 gate preacts
__device__ __half g_seq1h[(size_t)ROWS * 1024];   // lstm1 output (fp16)
__device__ __half g_hh0[2 * Bsz * UNITS];         // h ping (fp16)
__device__ __half g_hh1[2 * Bsz * UNITS];         // h pong (fp16)
__device__ __half g_emb16[VOCAB * EMB];
__device__ __half g_l1Wi16[(size_t)N2 * EMB];     // [4096][256]  (transposed)
__device__ __half g_l2Wi16[(size_t)N2 * 1024];    // [4096][1024] (transposed)
__device__ __half g_W1T[(size_t)1024 * 3072];     // [1024][3072] (transposed)
__device__ __half g_W2T[(size_t)512 * 1024];      // [512][1024]  (transposed)
__device__ float  g_bias1[N2];
__device__ float  g_bias2[N2];
__device__ __half g_feats16[Bsz * 3072];
__device__ __half g_x1h[Bsz * 1024];
__device__ __half g_x2h[Bsz * 512];
__device__ float  g_part[4 * Bsz * 1024];         // split-K partials (4 MB)

// group barrier state: 4 groups (bm x dir) of 32 blocks, separate cache lines
__device__ unsigned g_gcount[4][32];
__device__ volatile unsigned g_ggen[4][32];

__device__ __forceinline__ void group_barrier(int gid) {
    __threadfence();
    __syncthreads();
    if (threadIdx.x == 0) {
        unsigned gen = g_ggen[gid][0];
        if (atomicAdd(&g_gcount[gid][0], 1u) == 31u) {
            atomicExch(&g_gcount[gid][0], 0u);
            __threadfence();
            g_ggen[gid][0] = gen + 1;
        } else {
            while (g_ggen[gid][0] == gen) { }
        }
    }
    __syncthreads();
}

// ================= MMA / async / math helpers ==============================
__device__ __forceinline__ void mma_f16(float* d, const unsigned* a, const unsigned* b) {
    asm volatile(
        "mma.sync.aligned.m16n8k16.row.col.f32.f16.f16.f32 "
        "{%0,%1,%2,%3},{%4,%5,%6,%7},{%8,%9},{%0,%1,%2,%3};\n"
        : "+f"(d[0]), "+f"(d[1]), "+f"(d[2]), "+f"(d[3])
        : "r"(a[0]), "r"(a[1]), "r"(a[2]), "r"(a[3]), "r"(b[0]), "r"(b[1]));
}

__device__ __forceinline__ void ldsm_x4(unsigned* r, unsigned addr) {
    asm volatile("ldmatrix.sync.aligned.m8n8.x4.shared.b16 {%0,%1,%2,%3}, [%4];"
                 : "=r"(r[0]), "=r"(r[1]), "=r"(r[2]), "=r"(r[3]) : "r"(addr));
}

__device__ __forceinline__ void cp16(void* smem_dst, const void* gsrc) {
    unsigned s = (unsigned)__cvta_generic_to_shared(smem_dst);
    asm volatile("cp.async.cg.shared.global [%0], [%1], 16;\n" :: "r"(s), "l"(gsrc));
}

__device__ __forceinline__ float tanh_fast(float x) {
    float r;
    asm("tanh.approx.f32 %0, %1;" : "=f"(r) : "f"(x));
    return r;
}
__device__ __forceinline__ float sig_fast(float x) {
    return fmaf(tanh_fast(0.5f * x), 0.5f, 0.5f);
}

// ================= fused prologue: conversions + pooled mean ===============
#define PREP_BLOCKS 12034

__global__ void prep_kernel(const float* __restrict__ emb,
                            const float* __restrict__ l1fWi, const float* __restrict__ l1bWi,
                            const float* __restrict__ l2fWi, const float* __restrict__ l2bWi,
                            const float* __restrict__ W1, const float* __restrict__ W2,
                            const float* __restrict__ l1fb, const float* __restrict__ l1bb,
                            const float* __restrict__ l2fb, const float* __restrict__ l2bb,
                            const float* __restrict__ enc,
                            __half* __restrict__ emb16, __half* __restrict__ l1Wi16,
                            __half* __restrict__ l2Wi16, __half* __restrict__ W1T,
                            __half* __restrict__ W2T,
                            float* __restrict__ bias1, float* __restrict__ bias2,
                            float* __restrict__ pooled) {
    int bid = blockIdx.x, tid = threadIdx.x;
    if (bid < 1250) {
        int i0 = bid * 2048 + tid;
#pragma unroll
        for (int s = 0; s < 8; s++) {
            int i = i0 + s * 256;
            if (i < VOCAB * EMB) emb16[i] = __float2half(emb[i]);
        }
        return;
    }
    if (bid >= 9986) {
        int idx = (bid - 9986) * 256 + tid;
        int b = idx >> 11;
        int c = idx & 2047;
        const float* p = enc + (size_t)b * 100 * 2048 + c;
        float s = 0.f;
#pragma unroll 4
        for (int q = 0; q < 100; q++) s += p[q * 2048];
        pooled[idx] = s * 0.01f;
        return;
    }
    if (bid >= 9954) {
        int i = (bid - 9954) * 256 + tid;
        if (i < 4096) bias1[i] = (i < 2048) ? l1fb[i] : l1bb[i - 2048];
        else { int k = i - 4096; bias2[k] = (k < 2048) ? l2fb[k] : l2bb[k - 2048]; }
        return;
    }
    __shared__ float tile[32][33];
    const float* W; __half* out; int K, N, ti;
    if (bid < 1762)      { W = l1fWi; out = l1Wi16;                       K = 256;  N = 2048; ti = bid - 1250; }
    else if (bid < 2274) { W = l1bWi; out = l1Wi16 + (size_t)2048 * 256;  K = 256;  N = 2048; ti = bid - 1762; }
    else if (bid < 4322) { W = l2fWi; out = l2Wi16;                       K = 1024; N = 2048; ti = bid - 2274; }
    else if (bid < 6370) { W = l2bWi; out = l2Wi16 + (size_t)2048 * 1024; K = 1024; N = 2048; ti = bid - 4322; }
    else if (bid < 9442) { W = W1;    out = W1T;                          K = 3072; N = 1024; ti = bid - 6370; }
    else                 { W = W2;    out = W2T;                          K = 1024; N = 512;  ti = bid - 9442; }
    int ntx = N >> 5;
    int n0 = (ti % ntx) * 32, k0 = (ti / ntx) * 32;
    int tx = tid & 31, ty = tid >> 5;
    for (int i = ty; i < 32; i += 8)
        tile[i][tx] = W[(size_t)(k0 + i) * N + n0 + tx];
    __syncthreads();
    for (int i = ty; i < 32; i += 8)
        out[(size_t)(n0 + i) * K + k0 + tx] = __float2half(tile[tx][i]);
}

// ================= fp16 GEMM, 256x128 tile, 512 thr (projections) ==========
#define HAS 36
#define GAB (256*HAS)
#define GBB (128*HAS)
#define BIG_SMEM ((2*(GAB+GBB))*4)  // 110592 B

__global__ void __launch_bounds__(512)
h16_gemm_big(const __half* __restrict__ A, const __half* __restrict__ emb,
             const int* __restrict__ seq, int K,
             const __half* __restrict__ WT, const float* __restrict__ bias,
             __half* __restrict__ C, int cstride) {
    extern __shared__ unsigned sm[];
    unsigned* Asw = sm;                 // [2][256][HAS]
    unsigned* Bsw = sm + 2 * GAB;       // [2][128][HAS]

    int n0 = blockIdx.x * 128;
    int m0 = blockIdx.y * 256;
    int tid = threadIdx.x;
    int wid = tid >> 5, lane = tid & 31;
    int g = lane >> 2, tg = lane & 3;
    int wm = (wid >> 2) * 64;
    int wn = (wid & 3) * 32;

    int ar = tid >> 1;
    int aseg = tid & 1;
    const __half* Arow = seq ? (emb + (size_t)seq[m0 + ar] * K)
                             : (A + (size_t)(m0 + ar) * K);
    int br = tid >> 2;
    int bseg = tid & 3;
    const __half* Brow = WT + (size_t)(n0 + br) * K;

    int j8 = lane >> 3, r8 = lane & 7;
    unsigned smA = (unsigned)__cvta_generic_to_shared(Asw);
    unsigned smB = (unsigned)__cvta_generic_to_shared(Bsw);
    unsigned aoffL[4], boffL[2];
#pragma unroll
    for (int mi = 0; mi < 4; mi++)
        aoffL[mi] = ((wm + mi * 16 + (j8 & 1) * 8 + r8) * HAS + (j8 >> 1) * 4) * 4;
#pragma unroll
    for (int np = 0; np < 2; np++)
        boffL[np] = ((wn + np * 16 + (j8 >> 1) * 8 + r8) * HAS + (j8 & 1) * 4) * 4;

    int niter = K >> 6;

#define GSTAGE(IT, BUF) do {                                                   \
        int k0 = (IT) << 6;                                                    \
        unsigned* ad = Asw + (BUF) * GAB + ar * HAS + aseg * 16;               \
        const __half* as = Arow + k0 + aseg * 32;                              \
        cp16(ad, as); cp16(ad + 4, as + 8);                                    \
        cp16(ad + 8, as + 16); cp16(ad + 12, as + 24);                         \
        unsigned* bd = Bsw + (BUF) * GBB + br * HAS + bseg * 8;                \
        const __half* bs = Brow + k0 + bseg * 16;                              \
        cp16(bd, bs); cp16(bd + 4, bs + 8);                                    \
        asm volatile("cp.async.commit_group;\n");                              \
    } while (0)

    float acc[4][4][4] = {};

    GSTAGE(0, 0);
    for (int it = 0; it < niter; it++) {
        int buf = it & 1;
        if (it + 1 < niter) {
            GSTAGE(it + 1, buf ^ 1);
            asm volatile("cp.async.wait_group 1;\n");
        } else {
            asm volatile("cp.async.wait_group 0;\n");
        }
        __syncthreads();
        unsigned abase = smA + buf * GAB * 4;
        unsigned bbase = smB + buf * GBB * 4;
#pragma unroll
        for (int kk = 0; kk < 4; kk++) {
            unsigned koff = kk * 32;
            unsigned a[4][4], b[2][4];
#pragma unroll
            for (int mi = 0; mi < 4; mi++) ldsm_x4(a[mi], abase + aoffL[mi] + koff);
#pragma unroll
            for (int np = 0; np < 2; np++) ldsm_x4(b[np], bbase + boffL[np] + koff);
#pragma unroll
            for (int mi = 0; mi < 4; mi++) {
#pragma unroll
                for (int np = 0; np < 2; np++) {
                    mma_f16(acc[mi][np * 2],     a[mi], b[np]);
                    mma_f16(acc[mi][np * 2 + 1], a[mi], b[np] + 2);
                }
            }
        }
        __syncthreads();
    }
#undef GSTAGE

#pragma unroll
    for (int mi = 0; mi < 4; mi++) {
#pragma unroll
        for (int rh = 0; rh < 2; rh++) {
            int row = m0 + wm + mi * 16 + g + rh * 8;
#pragma unroll
            for (int ni = 0; ni < 4; ni++) {
                int cl = wn + ni * 8 + 2 * tg;
                float v0 = acc[mi][ni][rh * 2 + 0] + bias[n0 + cl];
                float v1 = acc[mi][ni][rh * 2 + 1] + bias[n0 + cl + 1];
                __half2 hv = __floats2half2_rn(v0, v1);
                *(__half2*)(C + (size_t)row * cstride + n0 + cl) = hv;
            }
        }
    }
}

// ================= fp16 split-K GEMM (MLP), 128x128, fp32 partials =========
#define HBUF (128*HAS)
#define H16_SMEM (4*HBUF*4)

__global__ void __launch_bounds__(256)
h16_splitk(const __half* __restrict__ A, int lda,
           const __half* __restrict__ WT, int ldw, int Ksp,
           float* __restrict__ part, int N, int MN) {
    extern __shared__ unsigned sm[];
    unsigned* Asw = sm;
    unsigned* Bsw = sm + 2 * HBUF;

    int n0 = blockIdx.x * 128;
    int m0 = blockIdx.y * 128;
    int koffb = blockIdx.z * Ksp;
    int tid = threadIdx.x;
    int wid = tid >> 5, lane = tid & 31;
    int g = lane >> 2, tg = lane & 3;
    int wm = (wid >> 2) * 64;
    int wn = (wid & 3) * 32;

    int ar = tid >> 1;
    int aseg = tid & 1;
    const __half* Arow = A + (size_t)(m0 + ar) * lda + koffb;
    const __half* Brow = WT + (size_t)(n0 + ar) * ldw + koffb;

    int j8 = lane >> 3, r8 = lane & 7;
    unsigned smA = (unsigned)__cvta_generic_to_shared(Asw);
    unsigned smB = (unsigned)__cvta_generic_to_shared(Bsw);
    unsigned aoffL[4], boffL[2];
#pragma unroll
    for (int mi = 0; mi < 4; mi++)
        aoffL[mi] = ((wm + mi * 16 + (j8 & 1) * 8 + r8) * HAS + (j8 >> 1) * 4) * 4;
#pragma unroll
    for (int np = 0; np < 2; np++)
        boffL[np] = ((wn + np * 16 + (j8 >> 1) * 8 + r8) * HAS + (j8 & 1) * 4) * 4;

    int niter = Ksp >> 6;

#define SSTAGE(IT, BUF) do {                                                   \
        int k0 = (IT) << 6;                                                    \
        unsigned* ad = Asw + (BUF) * HBUF + ar * HAS + aseg * 16;              \
        const __half* as = Arow + k0 + aseg * 32;                              \
        cp16(ad, as); cp16(ad + 4, as + 8);                                    \
        cp16(ad + 8, as + 16); cp16(ad + 12, as + 24);                         \
        unsigned* bd = Bsw + (BUF) * HBUF + ar * HAS + aseg * 16;              \
        const __half* bs = Brow + k0 + aseg * 32;                              \
        cp16(bd, bs); cp16(bd + 4, bs + 8);                                    \
        cp16(bd + 8, bs + 16); cp16(bd + 12, bs + 24);                         \
        asm volatile("cp.async.commit_group;\n");                              \
    } while (0)

    float acc[4][4][4] = {};

    SSTAGE(0, 0);
    for (int it = 0; it < niter; it++) {
        int buf = it & 1;
        if (it + 1 < niter) {
            SSTAGE(it + 1, buf ^ 1);
            asm volatile("cp.async.wait_group 1;\n");
        } else {
            asm volatile("cp.async.wait_group 0;\n");
        }
        __syncthreads();
        unsigned abase = smA + buf * HBUF * 4;
        unsigned bbase = smB + buf * HBUF * 4;
#pragma unroll
        for (int kk = 0; kk < 4; kk++) {
            unsigned koff = kk * 32;
            unsigned a[4][4], b[2][4];
#pragma unroll
            for (int mi = 0; mi < 4; mi++) ldsm_x4(a[mi], abase + aoffL[mi] + koff);
#pragma unroll
            for (int np = 0; np < 2; np++) ldsm_x4(b[np], bbase + boffL[np] + koff);
#pragma unroll
            for (int mi = 0; mi < 4; mi++) {
#pragma unroll
                for (int np = 0; np < 2; np++) {
                    mma_f16(acc[mi][np * 2],     a[mi], b[np]);
                    mma_f16(acc[mi][np * 2 + 1], a[mi], b[np] + 2);
                }
            }
        }
        __syncthreads();
    }
#undef SSTAGE

    float* pbase = part + (size_t)blockIdx.z * MN;
#pragma unroll
    for (int mi = 0; mi < 4; mi++) {
#pragma unroll
        for (int rh = 0; rh < 2; rh++) {
            int row = m0 + wm + mi * 16 + g + rh * 8;
#pragma unroll
            for (int ni = 0; ni < 4; ni++) {
                int cl = wn + ni * 8 + 2 * tg;
                *(float2*)(pbase + (size_t)row * N + n0 + cl) =
                    make_float2(acc[mi][ni][rh * 2 + 0], acc[mi][ni][rh * 2 + 1]);
            }
        }
    }
}

__global__ void splitk_reduce(const float* __restrict__ part, const float* __restrict__ bias,
                              __half* __restrict__ out, int MN, int Nmask, int SK) {
    int i = blockIdx.x * 256 + threadIdx.x;
    if (i >= MN) return;
    float s = bias[i & Nmask];
    for (int k = 0; k < SK; k++) s += part[(size_t)k * MN + i];
    s = fmaxf(s, 0.f);
    out[i] = __float2half(s);
}

// ================= persistent BiLSTM recurrence (R11 exact) ================
#define BS2 260
#define MS2 260
#define XS 36
#define ZS_STRIDE 68
#define REC_SMEM ((64*BS2 + 128*MS2 + 128*XS) * 4)   // 218112 B

__global__ void __launch_bounds__(256, 1)
rec_persistent(__half* __restrict__ hbuf0, __half* __restrict__ hbuf1,
               const float* __restrict__ WhF, const float* __restrict__ WhB,
               const __half* __restrict__ xw, const int* __restrict__ seq,
               __half* __restrict__ out_seq) {
    extern __shared__ unsigned smem_dyn[];
    unsigned* Bsw = smem_dyn;
    unsigned* Asw = smem_dyn + 64 * BS2;
    unsigned* Xsw = smem_dyn + 64 * BS2 + 128 * MS2;
    float* zs = (float*)Asw;

    int tid = threadIdx.x;
    int bn = blockIdx.x & 63;
    int bm = blockIdx.x >> 6;
    int dir = bn >> 5;
    int ub = (bn & 31) * 16;
    int m0 = bm * 128;
    int gid = bm * 2 + dir;
    const float* W = dir ? WhB : WhF;

    int wid = tid >> 5, lane = tid & 31;
    int g = lane >> 2, tg = lane & 3;
    int wm = (wid >> 1) * 32;
    int wn = (wid & 1) * 32;

    for (int jj = tid; jj < 64 * 256; jj += 256) {
        int k2 = jj >> 6, cl = jj & 63;
        int nc = (cl >> 4) * 512 + ub + (cl & 15);
        float lo = W[(size_t)(2 * k2) * G4 + nc];
        float hi = W[(size_t)(2 * k2 + 1) * G4 + nc];
        __half2 hv = __floats2half2_rn(lo, hi);
        Bsw[cl * BS2 + k2] = *(unsigned*)&hv;
    }

    int j8 = lane >> 3, r8 = lane & 7;
    unsigned smA = (unsigned)__cvta_generic_to_shared(Asw);
    unsigned smB = (unsigned)__cvta_generic_to_shared(Bsw);
    unsigned aoff[2], boff[2];
#pragma unroll
    for (int mi = 0; mi < 2; mi++)
        aoff[mi] = smA + ((wm + mi * 16 + (j8 & 1) * 8 + r8) * MS2 + (j8 >> 1) * 4) * 4;
#pragma unroll
    for (int np = 0; np < 2; np++)
        boff[np] = smB + ((wn + np * 16 + (j8 >> 1) * 8 + r8) * BS2 + (j8 & 1) * 4) * 4;

    float creg[8], hreg[8];
#pragma unroll
    for (int e = 0; e < 8; e++) { creg[e] = 0.f; hreg[e] = 0.f; }

    int ar = tid >> 1;
    int ah0 = (tid & 1) * 256;
    int xrow = tid >> 1;
    int xseg2 = (tid & 1) * 2;
    int grow = tid >> 1;
    int guu0 = (tid & 1) * 8;
    __syncthreads();

    {
        int te0 = dir ? (Tlen - 1) : 0;
        const __half* xrowp = xw + ((size_t)(m0 + xrow) * Tlen + te0) * N2 + dir * G4 + ub;
        unsigned* xd = Xsw + xrow * XS + xseg2 * 8;
#pragma unroll
        for (int s = 0; s < 2; s++) {
            const __half* src = xrowp + (xseg2 + s) * 512;
            cp16(xd + s * 8, src);
            cp16(xd + s * 8 + 4, src + 8);
        }
        asm volatile("cp.async.commit_group;\n");
    }

    for (int t = 0; t < Tlen; t++) {
        int te = dir ? (Tlen - 1 - t) : t;
        const __half* hcur = (t & 1) ? hbuf1 : hbuf0;
        __half* hnxt = (t & 1) ? hbuf0 : hbuf1;

        if (t > 0) {
            const __half* srch = hcur + dir * (Bsz * UNITS) + (size_t)(m0 + ar) * UNITS + ah0;
            unsigned* dstw = Asw + ar * MS2 + (ah0 >> 1);
#pragma unroll
            for (int i = 0; i < 32; i++) cp16(dstw + i * 4, srch + i * 8);
            asm volatile("cp.async.commit_group;\n");
        }
        asm volatile("cp.async.wait_group 0;\n");
        __syncthreads();

        float acc[2][4][4] = {};
        if (t > 0) {
#pragma unroll 4
            for (int kk = 0; kk < 32; kk++) {
                unsigned koff = kk * 32;
                unsigned a[2][4], b[2][4];
                ldsm_x4(a[0], aoff[0] + koff);
                ldsm_x4(a[1], aoff[1] + koff);
                ldsm_x4(b[0], boff[0] + koff);
                ldsm_x4(b[1], boff[1] + koff);
#pragma unroll
                for (int mi = 0; mi < 2; mi++) {
#pragma unroll
                    for (int np = 0; np < 2; np++) {
                        mma_f16(acc[mi][np * 2],     a[mi], b[np]);
                        mma_f16(acc[mi][np * 2 + 1], a[mi], b[np] + 2);
                    }
                }
            }
        }
        __syncthreads();

#pragma unroll
        for (int mi = 0; mi < 2; mi++) {
#pragma unroll
            for (int rh = 0; rh < 2; rh++) {
                int lrow = wm + mi * 16 + g + rh * 8;
#pragma unroll
                for (int ni = 0; ni < 4; ni++) {
                    int cl = wn + ni * 8 + 2 * tg;
                    int gate = cl >> 4, uu = cl & 15;
                    unsigned xu = Xsw[lrow * XS + gate * 8 + (uu >> 1)];
                    float2 xv = __half22float2(*(__half2*)&xu);
                    zs[lrow * ZS_STRIDE + cl]     = acc[mi][ni][rh * 2 + 0] + xv.x;
                    zs[lrow * ZS_STRIDE + cl + 1] = acc[mi][ni][rh * 2 + 1] + xv.y;
                }
            }
        }
        __syncthreads();

        if (t + 1 < Tlen) {
            int ten = dir ? (Tlen - 2 - t) : (t + 1);
            const __half* xrowp = xw + ((size_t)(m0 + xrow) * Tlen + ten) * N2 + dir * G4 + ub;
            unsigned* xd = Xsw + xrow * XS + xseg2 * 8;
#pragma unroll
            for (int s = 0; s < 2; s++) {
                const __half* src = xrowp + (xseg2 + s) * 512;
                cp16(xd + s * 8, src);
                cp16(xd + s * 8 + 4, src + 8);
            }
            asm volatile("cp.async.commit_group;\n");
        }

        {
            int b = m0 + grow;
            bool live = (seq[b * Tlen + te] != 0);
            const float* zb = zs + grow * ZS_STRIDE + guu0;
            float zi[8], zf[8], zg[8], zo[8];
            *(float4*)&zi[0] = *(const float4*)(zb);      *(float4*)&zi[4] = *(const float4*)(zb + 4);
            *(float4*)&zf[0] = *(const float4*)(zb + 16); *(float4*)&zf[4] = *(const float4*)(zb + 20);
            *(float4*)&zg[0] = *(const float4*)(zb + 32); *(float4*)&zg[4] = *(const float4*)(zb + 36);
            *(float4*)&zo[0] = *(const float4*)(zb + 48); *(float4*)&zo[4] = *(const float4*)(zb + 52);
#pragma unroll
            for (int e = 0; e < 8; e++) {
                float si = sig_fast(zi[e]);
                float sf = sig_fast(zf[e]);
                float so = sig_fast(zo[e]);
                float cn = sf * creg[e] + si * tanh_fast(zg[e]);
                float hn = so * tanh_fast(cn);
                if (live) { creg[e] = cn; hreg[e] = hn; }
            }
            __half2 p[4];
#pragma unroll
            for (int q = 0; q < 4; q++) p[q] = __floats2half2_rn(hreg[2 * q], hreg[2 * q + 1]);
            uint4 pk = *(uint4*)p;
            *(uint4*)(hnxt + dir * (Bsz * UNITS) + b * UNITS + ub + guu0) = pk;
            if (out_seq)
                *(uint4*)(out_seq + ((size_t)b * Tlen + te) * 1024 + dir * 512 + ub + guu0) = pk;
        }
        group_barrier(gid);
    }
}

// ---------------- feats16 = concat(pooled, h_final) ------------------------
__global__ void concat_kernel(const float* __restrict__ pooled,
                              const __half* __restrict__ h,
                              __half* __restrict__ feats) {
    int idx = blockIdx.x * blockDim.x + threadIdx.x;
    if (idx >= Bsz * 3072) return;
    int b = idx / 3072;
    int k = idx - b * 3072;
    __half v;
    if (k < 2048) v = __float2half(pooled[b * 2048 + k]);
    else {
        int kk = k - 2048;
        int dir = kk >> 9;
        int u = kk & 511;
        v = h[dir * 131072 + b * 512 + u];
    }
    feats[idx] = v;
}

// ---------------- final: sigmoid(x2 @ W3 + b3) -----------------------------
__global__ void final_kernel(const __half* __restrict__ x2, const float* __restrict__ W3,
                             const float* __restrict__ b3, float* __restrict__ out) {
    int b = blockIdx.x;
    float s = 0.f;
    for (int k = threadIdx.x; k < 512; k += 128)
        s += __half2float(x2[b * 512 + k]) * W3[k];
    for (int o = 16; o > 0; o >>= 1) s += __shfl_down_sync(0xffffffffu, s, o);
    __shared__ float red[4];
    if ((threadIdx.x & 31) == 0) red[threadIdx.x >> 5] = s;
    __syncthreads();
    if (threadIdx.x == 0) {
        float t = red[0] + red[1] + red[2] + red[3] + b3[0];
        out[b] = 1.f / (1.f + expf(-t));
    }
}

// ---------------------------------------------------------------------------
extern "C" void kernel_launch(void* const* d_in, const int* in_sizes, int n_in,
                              void* d_out, int out_size) {
    const float* enc    = (const float*)d_in[0];
    const int*   seq    = (const int*)d_in[1];
    const float* emb    = (const float*)d_in[2];
    const float* l1f_Wi = (const float*)d_in[3];
    const float* l1f_Wh = (const float*)d_in[4];
    const float* l1f_b  = (const float*)d_in[5];
    const float* l1b_Wi = (const float*)d_in[6];
    const float* l1b_Wh = (const float*)d_in[7];
    const float* l1b_b  = (const float*)d_in[8];
    const float* l2f_Wi = (const float*)d_in[9];
    const float* l2f_Wh = (const float*)d_in[10];
    const float* l2f_b  = (const float*)d_in[11];
    const float* l2b_Wi = (const float*)d_in[12];
    const float* l2b_Wh = (const float*)d_in[13];
    const float* l2b_b  = (const float*)d_in[14];
    const float* W1     = (const float*)d_in[15];
    const float* b1     = (const float*)d_in[16];
    const float* W2     = (const float*)d_in[17];
    const float* b2     = (const float*)d_in[18];
    const float* W3     = (const float*)d_in[19];
    const float* b3     = (const float*)d_in[20];
    float* out = (float*)d_out;

    float *pooled, *bias1, *bias2, *part;
    __half *xw16, *seq1h, *hh0, *hh1, *emb16, *l1Wi16, *l2Wi16, *W1T, *W2T, *feats16, *x1h, *x2h;
    cudaGetSymbolAddress((void**)&pooled, g_pooled);
    cudaGetSymbolAddress((void**)&xw16, g_xw16);
    cudaGetSymbolAddress((void**)&seq1h, g_seq1h);
    cudaGetSymbolAddress((void**)&hh0, g_hh0);
    cudaGetSymbolAddress((void**)&hh1, g_hh1);
    cudaGetSymbolAddress((void**)&emb16, g_emb16);
    cudaGetSymbolAddress((void**)&l1Wi16, g_l1Wi16);
    cudaGetSymbolAddress((void**)&l2Wi16, g_l2Wi16);
    cudaGetSymbolAddress((void**)&W1T, g_W1T);
    cudaGetSymbolAddress((void**)&W2T, g_W2T);
    cudaGetSymbolAddress((void**)&bias1, g_bias1);
    cudaGetSymbolAddress((void**)&bias2, g_bias2);
    cudaGetSymbolAddress((void**)&feats16, g_feats16);
    cudaGetSymbolAddress((void**)&x1h, g_x1h);
    cudaGetSymbolAddress((void**)&x2h, g_x2h);
    cudaGetSymbolAddress((void**)&part, g_part);

    cudaFuncSetAttribute(rec_persistent,
                         cudaFuncAttributeMaxDynamicSharedMemorySize, REC_SMEM);
    cudaFuncSetAttribute(h16_gemm_big,
                         cudaFuncAttributeMaxDynamicSharedMemorySize, BIG_SMEM);
    cudaFuncSetAttribute(h16_splitk,
                         cudaFuncAttributeMaxDynamicSharedMemorySize, H16_SMEM);

    __half* hfinal = hh0;   // t=63 (odd) writes hbuf0

    // 0: fused prologue (conversions + pooled mean)
    prep_kernel<<<PREP_BLOCKS, 256>>>(emb, l1f_Wi, l1b_Wi, l2f_Wi, l2b_Wi, W1, W2,
                                      l1f_b, l1b_b, l2f_b, l2b_b, enc,
                                      emb16, l1Wi16, l2Wi16, W1T, W2T,
                                      bias1, bias2, pooled);
    // 1: layer-1 input projection (256x128 big tile, fused gather)
    h16_gemm_big<<<dim3(N2 / 128, ROWS / 256), 512, BIG_SMEM>>>(
        nullptr, emb16, seq, EMB, l1Wi16, bias1, xw16, N2);
    // 2: layer-1 recurrence (R11 config)
    rec_persistent<<<128, 256, REC_SMEM>>>(hh0, hh1, l1f_Wh, l1b_Wh, xw16, seq, seq1h);
    // 3: layer-2 input projection (256x128 big tile)
    h16_gemm_big<<<dim3(N2 / 128, ROWS / 256), 512, BIG_SMEM>>>(
        seq1h, nullptr, nullptr, 1024, l2Wi16, bias2, xw16, N2);
    // 4: layer-2 recurrence
    rec_persistent<<<128, 256, REC_SMEM>>>(hh0, hh1, l2f_Wh, l2b_Wh, xw16, seq, nullptr);
    // 5: concat feats
    concat_kernel<<<(Bsz * 3072 + 255) / 256, 256>>>(pooled, hfinal, feats16);
    // 6-7: MLP layer 1 (split-K 4: 64 blocks)
    h16_splitk<<<dim3(1024 / 128, Bsz / 128, 4), 256, H16_SMEM>>>(
        feats16, 3072, W1T, 3072, 768, part, 1024, Bsz * 1024);
    splitk_reduce<<<(Bsz * 1024 + 255) / 256, 256>>>(part, b1, x1h, Bsz * 1024, 1023, 4);
    // 8-9: MLP layer 2 (split-K 4: 32 blocks)
    h16_splitk<<<dim3(512 / 128, Bsz / 128, 4), 256, H16_SMEM>>>(
        x1h, 1024, W2T, 1024, 256, part, 512, Bsz * 512);
    splitk_reduce<<<(Bsz * 512 + 255) / 256, 256>>>(part, b2, x2h, Bsz * 512, 511, 4);
    // 10: final sigmoid
    final_kernel<<<Bsz, 128>>>(x2h, W3, b3, out);
}